// round 5
// baseline (speedup 1.0000x reference)
#include <cuda_runtime.h>
#include <cstdint>

#define BB 64
#define NN 8192
#define WW 64
#define HH 4
#define EPSF 1e-8f
#define NCHUNK 64          // 8192 / 128 rows per block

// ---------------- scratch (device globals; no allocation allowed) ----------------
__device__ float g_e[BB * NN * HH];               // exp(beta*(cos-1)), layout [b][n][h]
__device__ float g_parte[BB * HH * NCHUNK];       // partial sums of e   [(b*4+h)*64 + chunk]
__device__ float g_partw[BB * HH * NCHUNK];       // partial sums of ws  [(b*4+h)*64 + chunk]
__device__ float g_parto[NCHUNK * BB * HH * WW];  // raw partial outputs [chunk][b][h][w]

__device__ __forceinline__ float softplusf(float x) {
    return (x > 20.f) ? x : log1pf(expf(x));
}
__device__ __forceinline__ unsigned long long pk2(float lo, float hi) {
    unsigned long long r;
    asm("mov.b64 %0, {%1, %2};" : "=l"(r) : "f"(lo), "f"(hi));
    return r;
}
__device__ __forceinline__ void upk2(unsigned long long v, float& lo, float& hi) {
    asm("mov.b64 {%0, %1}, %2;" : "=f"(lo), "=f"(hi) : "l"(v));
}
__device__ __forceinline__ unsigned long long ffma2(unsigned long long a,
                                                    unsigned long long b,
                                                    unsigned long long c) {
    unsigned long long d;
    asm("fma.rn.f32x2 %0, %1, %2, %3;" : "=l"(d) : "l"(a), "l"(b), "l"(c));
    return d;
}

// =====================================================================
// Kernel A: content addressing -> e = exp(beta*(cos - 1)), + chunk sums of e
// grid (64, 64), block 128. One thread per memory row.
// SMEM tile 128 rows @ stride 66 floats: LDS.64 by lane=row is conflict-free.
// All FMA work in packed fma.rn.f32x2 (FFMA2).
// =====================================================================
__global__ void __launch_bounds__(128) k_scores(const float* __restrict__ mem,
                                                const float* __restrict__ ctrl) {
    __shared__ float s_mem[128 * 66];                  // 33792 B
    __shared__ float s_keys[256];
    __shared__ unsigned long long s_kp[128];           // packed key pairs [h*32 + j]
    __shared__ float s_nk[4], s_beta[4];
    __shared__ float4 s_wr[4];

    const int b   = blockIdx.y;
    const int tid = threadIdx.x;
    const float* cb = ctrl + b * 280;

    s_keys[tid]       = tanhf(cb[tid]);
    s_keys[tid + 128] = tanhf(cb[tid + 128]);
    if (tid < 4) s_beta[tid] = softplusf(cb[256 + tid]);
    __syncthreads();
    s_kp[tid] = pk2(s_keys[2 * tid], s_keys[2 * tid + 1]);
    if (tid < 4) {
        const float* kk = s_keys + tid * 64;
        float s = 0.f;
        #pragma unroll
        for (int w = 0; w < 64; w++) s = fmaf(kk[w], kk[w], s);
        s_nk[tid] = sqrtf(s);
    }

    // stage 128 rows (32 KB) coalesced; row stride 66 floats
    const int n0 = blockIdx.x * 128;
    const float4* src = (const float4*)(mem + ((size_t)b * NN + n0) * WW);
    #pragma unroll
    for (int i = 0; i < 16; i++) {
        int idx = tid + i * 128;                // 0..2047 float4
        int rr = idx >> 4, cc = idx & 15;
        float4 v = src[idx];
        float* dst = s_mem + rr * 66 + cc * 4;
        *(float2*)dst       = make_float2(v.x, v.y);
        *(float2*)(dst + 2) = make_float2(v.z, v.w);
    }
    __syncthreads();

    const unsigned long long* rp = (const unsigned long long*)(s_mem + tid * 66);
    unsigned long long nm = 0ull, d0 = 0ull, d1 = 0ull, d2 = 0ull, d3 = 0ull;
    #pragma unroll 8
    for (int j = 0; j < 32; j++) {
        unsigned long long m = rp[j];
        nm = ffma2(m, m, nm);
        d0 = ffma2(m, s_kp[j],      d0);
        d1 = ffma2(m, s_kp[32 + j], d1);
        d2 = ffma2(m, s_kp[64 + j], d2);
        d3 = ffma2(m, s_kp[96 + j], d3);
    }
    float lo, hi, nm2, dd0, dd1, dd2, dd3;
    upk2(nm, lo, hi); nm2 = lo + hi;
    upk2(d0, lo, hi); dd0 = lo + hi;
    upk2(d1, lo, hi); dd1 = lo + hi;
    upk2(d2, lo, hi); dd2 = lo + hi;
    upk2(d3, lo, hi); dd3 = lo + hi;

    const float nmr = sqrtf(nm2);
    float4 e;
    e.x = expf(s_beta[0] * (dd0 / (nmr * s_nk[0] + EPSF) - 1.f));
    e.y = expf(s_beta[1] * (dd1 / (nmr * s_nk[1] + EPSF) - 1.f));
    e.z = expf(s_beta[2] * (dd2 / (nmr * s_nk[2] + EPSF) - 1.f));
    e.w = expf(s_beta[3] * (dd3 / (nmr * s_nk[3] + EPSF) - 1.f));
    *(float4*)(g_e + ((size_t)b * NN + n0 + tid) * 4) = e;

    // block sums of e per head
    float4 v = e;
    #pragma unroll
    for (int off = 16; off > 0; off >>= 1) {
        v.x += __shfl_down_sync(0xffffffffu, v.x, off);
        v.y += __shfl_down_sync(0xffffffffu, v.y, off);
        v.z += __shfl_down_sync(0xffffffffu, v.z, off);
        v.w += __shfl_down_sync(0xffffffffu, v.w, off);
    }
    if ((tid & 31) == 0) s_wr[tid >> 5] = v;
    __syncthreads();
    if (tid == 0) {
        float4 t = s_wr[0];
        #pragma unroll
        for (int i = 1; i < 4; i++) {
            float4 a = s_wr[i];
            t.x += a.x; t.y += a.y; t.z += a.z; t.w += a.w;
        }
        float* p = g_parte + b * 4 * NCHUNK + blockIdx.x;
        p[0] = t.x; p[NCHUNK] = t.y; p[2 * NCHUNK] = t.z; p[3 * NCHUNK] = t.w;
    }
}

// =====================================================================
// Kernel C (fused weights + read):
//  prologue: per-row w_sharp = (gate-interp + circular shift + sharpen), packed
//  main: raw partial read accumulation (normalization deferred to kD)
// grid (64, 64), block 128. thread=(rsub 0..7, w4 0..15); 16 rows each.
// =====================================================================
__global__ void __launch_bounds__(128) k_read(const float* __restrict__ mem,
                                              const float* __restrict__ ctrl,
                                              const float* __restrict__ prev) {
    __shared__ float s_mem[128][68];                  // 34816 B, reused as s_red
    __shared__ unsigned long long s_wp[4][128];       // packed (w,w) per head per row
    __shared__ float s_g[4], s_sh0[4], s_sh1[4], s_sh2[4], s_gam[4], s_einv[4];
    __shared__ float4 s_wr[4];

    const int b   = blockIdx.y;
    const int tid = threadIdx.x;
    const int n0  = blockIdx.x * 128;

    if (tid < 4) {
        const float* cb = ctrl + b * 280;
        s_g[tid]   = 1.f / (1.f + expf(-cb[260 + tid]));
        s_gam[tid] = 1.f + softplusf(cb[276 + tid]);
        float a0 = cb[264 + tid * 3], a1 = cb[265 + tid * 3], a2 = cb[266 + tid * 3];
        float mx = fmaxf(a0, fmaxf(a1, a2));
        float e0 = expf(a0 - mx), e1 = expf(a1 - mx), e2 = expf(a2 - mx);
        float inv3 = 1.f / (e0 + e1 + e2);
        s_sh0[tid] = e0 * inv3; s_sh1[tid] = e1 * inv3; s_sh2[tid] = e2 * inv3;
        const float* pe = g_parte + (b * 4 + tid) * NCHUNK;
        float s = 0.f;
        #pragma unroll 8
        for (int c = 0; c < NCHUNK; c++) s += pe[c];
        s_einv[tid] = 1.f / s;                         // softmax denom (no EPS, per ref)
    }
    __syncthreads();

    // per-row sharpened weights
    {
        const int n  = n0 + tid;
        const int nm = (n - 1) & (NN - 1);
        const int np = (n + 1) & (NN - 1);
        const float4* eb = (const float4*)(g_e + (size_t)b * NN * 4);
        float4 em4 = eb[nm], ec4 = eb[n], ep4 = eb[np];
        float emv[4] = {em4.x, em4.y, em4.z, em4.w};
        float ecv[4] = {ec4.x, ec4.y, ec4.z, ec4.w};
        float epv[4] = {ep4.x, ep4.y, ep4.z, ep4.w};
        const float* pb = prev + (size_t)b * HH * NN;

        float4 wv;
        float* wvp = (float*)&wv;
        #pragma unroll
        for (int h = 0; h < 4; h++) {
            float g = s_g[h], inv = s_einv[h], om = 1.f - g;
            float wim = fmaf(g, emv[h] * inv, om * pb[h * NN + nm]);
            float wic = fmaf(g, ecv[h] * inv, om * pb[h * NN + n]);
            float wip = fmaf(g, epv[h] * inv, om * pb[h * NN + np]);
            float wsf = s_sh0[h] * wim + s_sh1[h] * wic + s_sh2[h] * wip;
            float ws  = __powf(wsf, s_gam[h]);         // wsf > 0 always
            s_wp[h][tid] = pk2(ws, ws);
            wvp[h] = ws;
        }
        // block sums of ws per head -> g_partw
        float4 v = wv;
        #pragma unroll
        for (int off = 16; off > 0; off >>= 1) {
            v.x += __shfl_down_sync(0xffffffffu, v.x, off);
            v.y += __shfl_down_sync(0xffffffffu, v.y, off);
            v.z += __shfl_down_sync(0xffffffffu, v.z, off);
            v.w += __shfl_down_sync(0xffffffffu, v.w, off);
        }
        if ((tid & 31) == 0) s_wr[tid >> 5] = v;
    }
    __syncthreads();
    if (tid == 0) {
        float4 t = s_wr[0];
        #pragma unroll
        for (int i = 1; i < 4; i++) {
            float4 a = s_wr[i];
            t.x += a.x; t.y += a.y; t.z += a.z; t.w += a.w;
        }
        float* p = g_partw + b * 4 * NCHUNK + blockIdx.x;
        p[0] = t.x; p[NCHUNK] = t.y; p[2 * NCHUNK] = t.z; p[3 * NCHUNK] = t.w;
    }

    // stage memory tile (coalesced)
    {
        const float4* src = (const float4*)(mem + ((size_t)b * NN + n0) * WW);
        #pragma unroll
        for (int i = 0; i < 16; i++) {
            int idx = tid + i * 128;
            *(float4*)&s_mem[idx >> 4][(idx & 15) * 4] = src[idx];
        }
    }
    __syncthreads();

    const int rsub = tid >> 4;     // 0..7
    const int w4   = tid & 15;     // 0..15
    unsigned long long a0l = 0, a0h = 0, a1l = 0, a1h = 0;
    unsigned long long a2l = 0, a2h = 0, a3l = 0, a3h = 0;

    #pragma unroll 4
    for (int rr = 0; rr < 16; rr++) {
        int r = rr * 8 + rsub;
        ulonglong2 m = *(const ulonglong2*)&s_mem[r][w4 * 4];
        unsigned long long w0 = s_wp[0][r], w1 = s_wp[1][r];
        unsigned long long w2 = s_wp[2][r], w3 = s_wp[3][r];
        a0l = ffma2(w0, m.x, a0l); a0h = ffma2(w0, m.y, a0h);
        a1l = ffma2(w1, m.x, a1l); a1h = ffma2(w1, m.y, a1h);
        a2l = ffma2(w2, m.x, a2l); a2h = ffma2(w2, m.y, a2h);
        a3l = ffma2(w3, m.x, a3l); a3h = ffma2(w3, m.y, a3h);
    }

    __syncthreads();                        // tile consumed; reuse s_mem as reduction buf
    float4* s_red = (float4*)s_mem;         // [rsub][h*16 + w4]
    {
        float4 t;
        upk2(a0l, t.x, t.y); upk2(a0h, t.z, t.w); s_red[rsub * 64 +  0 + w4] = t;
        upk2(a1l, t.x, t.y); upk2(a1h, t.z, t.w); s_red[rsub * 64 + 16 + w4] = t;
        upk2(a2l, t.x, t.y); upk2(a2h, t.z, t.w); s_red[rsub * 64 + 32 + w4] = t;
        upk2(a3l, t.x, t.y); upk2(a3h, t.z, t.w); s_red[rsub * 64 + 48 + w4] = t;
    }
    __syncthreads();
    if (tid < 64) {
        float4 acc = s_red[tid];
        #pragma unroll
        for (int k = 1; k < 8; k++) {
            float4 a = s_red[k * 64 + tid];
            acc.x += a.x; acc.y += a.y; acc.z += a.z; acc.w += a.w;
        }
        // tid = h*16 + w4 -> output offset h*64 + w4*4 = tid*4 (raw, unnormalized)
        *(float4*)(g_parto + (size_t)blockIdx.x * (BB * HH * WW) + b * 256 + tid * 4) = acc;
    }
}

// =====================================================================
// Kernel D: out[b,h,w] = (sum_c parto) / (sum_c partw + EPS)
// grid 32, block 128, float4 per thread (4096 threads).
// =====================================================================
__global__ void __launch_bounds__(128) k_final(float* __restrict__ out) {
    __shared__ float s_inv[8];
    const int i4  = blockIdx.x * 128 + threadIdx.x;   // 0..4095 float4 index
    const int bh0 = (blockIdx.x * 128) >> 4;          // first (b,h) group of block
    if (threadIdx.x < 8) {
        const float* pw = g_partw + (bh0 + threadIdx.x) * NCHUNK;
        float s = 0.f;
        #pragma unroll 8
        for (int c = 0; c < NCHUNK; c++) s += pw[c];
        s_inv[threadIdx.x] = 1.f / (s + EPSF);
    }
    __syncthreads();
    float4 acc = make_float4(0.f, 0.f, 0.f, 0.f);
    #pragma unroll 8
    for (int c = 0; c < NCHUNK; c++) {
        float4 a = *(const float4*)(g_parto + (size_t)c * (BB * HH * WW) + i4 * 4);
        acc.x += a.x; acc.y += a.y; acc.z += a.z; acc.w += a.w;
    }
    const float inv = s_inv[(i4 >> 4) - bh0];
    acc.x *= inv; acc.y *= inv; acc.z *= inv; acc.w *= inv;
    *(float4*)(out + i4 * 4) = acc;
}

// =====================================================================
extern "C" void kernel_launch(void* const* d_in, const int* in_sizes, int n_in,
                              void* d_out, int out_size) {
    const float* mem  = nullptr;
    const float* ctrl = nullptr;
    const float* prev = nullptr;
    for (int i = 0; i < n_in; i++) {
        if (in_sizes[i] == BB * NN * WW)      mem  = (const float*)d_in[i];
        else if (in_sizes[i] == BB * 280)     ctrl = (const float*)d_in[i];
        else if (in_sizes[i] == BB * HH * NN) prev = (const float*)d_in[i];
    }

    dim3 grid(NCHUNK, BB);
    k_scores<<<grid, 128>>>(mem, ctrl);
    k_read  <<<grid, 128>>>(mem, ctrl, prev);
    k_final <<<32,   128>>>((float*)d_out);
}

// round 7
// speedup vs baseline: 1.4539x; 1.4539x over previous
#include <cuda_runtime.h>
#include <cstdint>

#define BB 64
#define NN 8192
#define WW 64
#define EPSF 1e-8f
#define NCH 64            // 8192 / 128 rows per tile

typedef unsigned long long ull;

// ---------------- scratch (device globals; no allocation allowed) ----------------
__device__ __align__(16) float  g_keys[BB * 256];      // tanh(keys) [b][h][64]
__device__ __align__(16) float  g_nk[BB * 4];          // ||key||
__device__ __align__(16) float  g_beta[BB * 4];
__device__ __align__(16) float4 g_scA[BB * 4];         // {gate, gamma, 0, 0}
__device__ __align__(16) float4 g_scB[BB * 4];         // {sh0, sh1, sh2, 0}
__device__ float  g_einv[BB * 4];                      // 1 / sum(e)
__device__ __align__(16) float g_e[BB * NN * 4];       // [b][n][h]
__device__ float g_parte[BB * 4 * NCH];
__device__ float g_partw[BB * 4 * NCH];
__device__ __align__(16) float g_parto[NCH * BB * 256];// [chunk][b][h*64+w]

__device__ __forceinline__ float softplusf(float x) {
    return (x > 20.f) ? x : log1pf(expf(x));
}
__device__ __forceinline__ ull pk2(float lo, float hi) {
    ull r; asm("mov.b64 %0, {%1, %2};" : "=l"(r) : "f"(lo), "f"(hi)); return r;
}
__device__ __forceinline__ void upk2(ull v, float& lo, float& hi) {
    asm("mov.b64 {%0, %1}, %2;" : "=f"(lo), "=f"(hi) : "l"(v));
}
__device__ __forceinline__ ull ffma2(ull a, ull b, ull c) {
    ull d; asm("fma.rn.f32x2 %0, %1, %2, %3;" : "=l"(d) : "l"(a), "l"(b), "l"(c)); return d;
}

// =====================================================================
// k_prep: tanh(keys), key norms, betas, per-head scalars.  grid 64, block 256.
// =====================================================================
__global__ void __launch_bounds__(256) k_prep(const float* __restrict__ ctrl) {
    __shared__ float sk[256];
    const int b = blockIdx.x, t = threadIdx.x;
    const float* cb = ctrl + b * 280;
    float kv = tanhf(cb[t]);
    sk[t] = kv;
    g_keys[b * 256 + t] = kv;
    __syncthreads();
    if (t < 4) {
        float s = 0.f;
        #pragma unroll
        for (int w = 0; w < 64; w++) { float k = sk[t * 64 + w]; s = fmaf(k, k, s); }
        g_nk[b * 4 + t]   = sqrtf(s);
        g_beta[b * 4 + t] = softplusf(cb[256 + t]);
        float gate  = 1.f / (1.f + expf(-cb[260 + t]));
        float gamma = 1.f + softplusf(cb[276 + t]);
        float a0 = cb[264 + t * 3], a1 = cb[265 + t * 3], a2 = cb[266 + t * 3];
        float mx = fmaxf(a0, fmaxf(a1, a2));
        float e0 = expf(a0 - mx), e1 = expf(a1 - mx), e2 = expf(a2 - mx);
        float inv3 = 1.f / (e0 + e1 + e2);
        g_scA[b * 4 + t] = make_float4(gate, gamma, 0.f, 0.f);
        g_scB[b * 4 + t] = make_float4(e0 * inv3, e1 * inv3, e2 * inv3, 0.f);
    }
}

// =====================================================================
// k_scores: e = exp(beta*(cos-1)) + per-chunk e-sums.
// grid (64, 64), block 256. Tile 128 rows. Lane = (g = row-of-pair, w4 = chunk).
// Coalesced LDG.128 (512B/warp-inst), keys in registers, shfl-butterfly dots.
// =====================================================================
__global__ void __launch_bounds__(256) k_scores(const float* __restrict__ mem) {
    __shared__ float  s_dot[128][4];
    __shared__ float  s_nm[128];
    __shared__ float4 s_es[4];

    const int t   = threadIdx.x;
    const int w4  = t & 15;
    const int g   = (t >> 4) & 1;
    const int wid = t >> 5;
    const int b   = blockIdx.y;
    const int n0  = blockIdx.x * 128;

    // keys for my 16B chunk, all 4 heads (registers)
    ull kk[4][2];
    #pragma unroll
    for (int h = 0; h < 4; h++) {
        ulonglong2 kv = *(const ulonglong2*)(g_keys + b * 256 + h * 64 + w4 * 4);
        kk[h][0] = kv.x; kk[h][1] = kv.y;
    }

    const float* rowbase = mem + ((size_t)b * NN + n0 + wid * 16 + g) * WW + w4 * 4;

    float4 m = *(const float4*)rowbase;
    #pragma unroll
    for (int it = 0; it < 8; it++) {
        float4 mn = m;
        if (it < 7) mn = *(const float4*)(rowbase + (it + 1) * 128);  // +2 rows

        ull m01 = pk2(m.x, m.y), m23 = pk2(m.z, m.w);
        ull nm = ffma2(m01, m01, 0ull);  nm = ffma2(m23, m23, nm);
        ull d0 = ffma2(m01, kk[0][0], 0ull); d0 = ffma2(m23, kk[0][1], d0);
        ull d1 = ffma2(m01, kk[1][0], 0ull); d1 = ffma2(m23, kk[1][1], d1);
        ull d2 = ffma2(m01, kk[2][0], 0ull); d2 = ffma2(m23, kk[2][1], d2);
        ull d3 = ffma2(m01, kk[3][0], 0ull); d3 = ffma2(m23, kk[3][1], d3);

        float lo, hi;
        upk2(nm, lo, hi); float vn  = lo + hi;
        upk2(d0, lo, hi); float v0  = lo + hi;
        upk2(d1, lo, hi); float v1  = lo + hi;
        upk2(d2, lo, hi); float v2  = lo + hi;
        upk2(d3, lo, hi); float v3  = lo + hi;
        #pragma unroll
        for (int s = 8; s > 0; s >>= 1) {
            vn += __shfl_xor_sync(0xffffffffu, vn, s);
            v0 += __shfl_xor_sync(0xffffffffu, v0, s);
            v1 += __shfl_xor_sync(0xffffffffu, v1, s);
            v2 += __shfl_xor_sync(0xffffffffu, v2, s);
            v3 += __shfl_xor_sync(0xffffffffu, v3, s);
        }
        if (w4 == 0) {
            int r = wid * 16 + it * 2 + g;
            *(float4*)&s_dot[r][0] = make_float4(v0, v1, v2, v3);
            s_nm[r] = vn;
        }
        m = mn;
    }
    __syncthreads();

    if (t < 128) {
        float4 d  = *(const float4*)&s_dot[t][0];
        float nmr = sqrtf(s_nm[t]);
        float4 nk = *(const float4*)(g_nk + b * 4);
        float4 be = *(const float4*)(g_beta + b * 4);
        float4 e;
        e.x = __expf(be.x * (__fdividef(d.x, nmr * nk.x + EPSF) - 1.f));
        e.y = __expf(be.y * (__fdividef(d.y, nmr * nk.y + EPSF) - 1.f));
        e.z = __expf(be.z * (__fdividef(d.z, nmr * nk.z + EPSF) - 1.f));
        e.w = __expf(be.w * (__fdividef(d.w, nmr * nk.w + EPSF) - 1.f));
        *(float4*)(g_e + ((size_t)b * NN + n0 + t) * 4) = e;

        float4 v = e;
        #pragma unroll
        for (int s = 16; s > 0; s >>= 1) {
            v.x += __shfl_xor_sync(0xffffffffu, v.x, s);
            v.y += __shfl_xor_sync(0xffffffffu, v.y, s);
            v.z += __shfl_xor_sync(0xffffffffu, v.z, s);
            v.w += __shfl_xor_sync(0xffffffffu, v.w, s);
        }
        if ((t & 31) == 0) s_es[t >> 5] = v;
    }
    __syncthreads();
    if (t == 0) {
        float4 a = s_es[0], c1 = s_es[1], c2 = s_es[2], c3 = s_es[3];
        float* p = g_parte + b * 4 * NCH + blockIdx.x;
        p[0]       = a.x + c1.x + c2.x + c3.x;
        p[NCH]     = a.y + c1.y + c2.y + c3.y;
        p[2 * NCH] = a.z + c1.z + c2.z + c3.z;
        p[3 * NCH] = a.w + c1.w + c2.w + c3.w;
    }
}

// =====================================================================
// k_mid: einv[b][h] = 1 / sum_c parte.  grid 64, block 128.
// =====================================================================
__global__ void __launch_bounds__(128) k_mid() {
    const int b = blockIdx.x, t = threadIdx.x;
    const int h = t >> 5, lane = t & 31;
    const float* p = g_parte + (b * 4 + h) * NCH;
    float v = p[lane] + p[lane + 32];
    #pragma unroll
    for (int s = 16; s > 0; s >>= 1) v += __shfl_xor_sync(0xffffffffu, v, s);
    if (lane == 0) g_einv[b * 4 + h] = 1.f / v;
}

// =====================================================================
// k_read: weights prologue + unnormalized partial read. REVERSED (chunk,batch)
// order for L2 ping-pong reuse of `mem` with k_scores.
// grid (64, 64), block 256. Lane = (rsub = t>>4, w4 = t&15): coalesced LDG.
// =====================================================================
__global__ void __launch_bounds__(256) k_read(const float* __restrict__ mem,
                                              const float* __restrict__ prev) {
    __shared__ ull    s_wp[4][128];         // packed (w,w) per head per row
    __shared__ float  s_pw[8][2];
    __shared__ float4 s_red[16][4][16];     // [rsub][h][w4]

    const int t  = threadIdx.x;
    const int bx = (NCH - 1) - blockIdx.x;  // reversed
    const int b  = (BB  - 1) - blockIdx.y;  // reversed
    const int n0 = bx * 128;

    // ---- prologue: w_sharp for 128 rows x 4 heads (2 heads per thread) ----
    {
        const int r    = t & 127;
        const int half = t >> 7;            // 0 -> heads 0,1 ; 1 -> heads 2,3
        const int n    = n0 + r;
        const int nmi  = (n - 1) & (NN - 1);
        const int npi  = (n + 1) & (NN - 1);
        const float4* eb = (const float4*)g_e + (size_t)b * NN;
        float4 em = eb[nmi], ec = eb[n], ep = eb[npi];
        float eM0 = half ? em.z : em.x, eC0 = half ? ec.z : ec.x, eP0 = half ? ep.z : ep.x;
        float eM1 = half ? em.w : em.y, eC1 = half ? ec.w : ec.y, eP1 = half ? ep.w : ep.y;

        float wsv0, wsv1;
        #pragma unroll
        for (int j = 0; j < 2; j++) {
            const int h = half * 2 + j;
            float4 A  = g_scA[b * 4 + h];
            float4 Bv = g_scB[b * 4 + h];
            float ei  = g_einv[b * 4 + h];
            float gg  = A.x, om = 1.f - gg;
            const float* pb = prev + ((size_t)b * 4 + h) * NN;
            float eM = j ? eM1 : eM0, eC = j ? eC1 : eC0, eP = j ? eP1 : eP0;
            float wim = fmaf(gg, eM * ei, om * pb[nmi]);
            float wic = fmaf(gg, eC * ei, om * pb[n]);
            float wip = fmaf(gg, eP * ei, om * pb[npi]);
            float wsf = Bv.x * wim + Bv.y * wic + Bv.z * wip;
            float ws  = __powf(wsf, A.y);
            s_wp[h][r] = pk2(ws, ws);
            if (j) wsv1 = ws; else wsv0 = ws;
        }
        float v0 = wsv0, v1 = wsv1;
        #pragma unroll
        for (int s = 16; s > 0; s >>= 1) {
            v0 += __shfl_xor_sync(0xffffffffu, v0, s);
            v1 += __shfl_xor_sync(0xffffffffu, v1, s);
        }
        if ((t & 31) == 0) { s_pw[t >> 5][0] = v0; s_pw[t >> 5][1] = v1; }
    }
    __syncthreads();
    if (t < 4) {
        const int h = t;
        const int wbase = (h >> 1) * 4, j = h & 1;
        float s = s_pw[wbase][j] + s_pw[wbase + 1][j] + s_pw[wbase + 2][j] + s_pw[wbase + 3][j];
        g_partw[(b * 4 + h) * NCH + bx] = s;
    }

    // ---- main: accumulate 128 rows, coalesced global loads ----
    const int rsub = t >> 4;
    const int w4   = t & 15;
    const float* base = mem + ((size_t)b * NN + n0 + rsub) * WW + w4 * 4;

    ull a00 = 0, a01 = 0, a10 = 0, a11 = 0, a20 = 0, a21 = 0, a30 = 0, a31 = 0;
    float4 m = *(const float4*)base;
    #pragma unroll
    for (int k = 0; k < 8; k++) {
        float4 mn = m;
        if (k < 7) mn = *(const float4*)(base + (size_t)(k + 1) * 16 * WW);
        const int r = k * 16 + rsub;
        ull w0 = s_wp[0][r], w1 = s_wp[1][r], w2 = s_wp[2][r], w3 = s_wp[3][r];
        ull m01 = pk2(m.x, m.y), m23 = pk2(m.z, m.w);
        a00 = ffma2(w0, m01, a00); a01 = ffma2(w0, m23, a01);
        a10 = ffma2(w1, m01, a10); a11 = ffma2(w1, m23, a11);
        a20 = ffma2(w2, m01, a20); a21 = ffma2(w2, m23, a21);
        a30 = ffma2(w3, m01, a30); a31 = ffma2(w3, m23, a31);
        m = mn;
    }

    {
        float4 o; float lo, hi;
        upk2(a00, lo, hi); o.x = lo; o.y = hi; upk2(a01, lo, hi); o.z = lo; o.w = hi;
        s_red[rsub][0][w4] = o;
        upk2(a10, lo, hi); o.x = lo; o.y = hi; upk2(a11, lo, hi); o.z = lo; o.w = hi;
        s_red[rsub][1][w4] = o;
        upk2(a20, lo, hi); o.x = lo; o.y = hi; upk2(a21, lo, hi); o.z = lo; o.w = hi;
        s_red[rsub][2][w4] = o;
        upk2(a30, lo, hi); o.x = lo; o.y = hi; upk2(a31, lo, hi); o.z = lo; o.w = hi;
        s_red[rsub][3][w4] = o;
    }
    __syncthreads();
    if (t < 64) {
        const int h = t >> 4, w = t & 15;
        float4 acc = s_red[0][h][w];
        #pragma unroll
        for (int k = 1; k < 16; k++) {
            float4 a = s_red[k][h][w];
            acc.x += a.x; acc.y += a.y; acc.z += a.z; acc.w += a.w;
        }
        // raw partials; normalize in k_final.  float4 idx = bx*4096 + b*64 + t
        *(((float4*)g_parto) + (size_t)bx * 4096 + b * 64 + t) = acc;
    }
}

// =====================================================================
// k_final: out[b][h][w] = (sum_c parto) / (sum_c partw + EPS). grid 64, block 256.
// =====================================================================
__global__ void __launch_bounds__(256) k_final(float* __restrict__ out) {
    __shared__ float  s_winv[4];
    __shared__ float4 s_acc[4][64];
    const int b = blockIdx.x, t = threadIdx.x;
    const int i4 = t & 63, cg = t >> 6;

    if (t < 128) {
        const int h = t >> 5, lane = t & 31;
        const float* pw = g_partw + (b * 4 + h) * NCH;
        float v = pw[lane] + pw[lane + 32];
        #pragma unroll
        for (int s = 16; s > 0; s >>= 1) v += __shfl_xor_sync(0xffffffffu, v, s);
        if (lane == 0) s_winv[h] = 1.f / (v + EPSF);
    }

    float4 acc = make_float4(0.f, 0.f, 0.f, 0.f);
    const float4* po = (const float4*)g_parto;
    #pragma unroll
    for (int j = 0; j < 16; j++) {
        const int c = cg * 16 + j;
        float4 a = po[(size_t)c * 4096 + b * 64 + i4];
        acc.x += a.x; acc.y += a.y; acc.z += a.z; acc.w += a.w;
    }
    s_acc[cg][i4] = acc;
    __syncthreads();
    if (t < 64) {
        float4 r = s_acc[0][t], c1 = s_acc[1][t], c2 = s_acc[2][t], c3 = s_acc[3][t];
        r.x += c1.x + c2.x + c3.x;
        r.y += c1.y + c2.y + c3.y;
        r.z += c1.z + c2.z + c3.z;
        r.w += c1.w + c2.w + c3.w;
        float inv = s_winv[t >> 4];
        r.x *= inv; r.y *= inv; r.z *= inv; r.w *= inv;
        *(((float4*)out) + b * 64 + t) = r;
    }
}

// =====================================================================
extern "C" void kernel_launch(void* const* d_in, const int* in_sizes, int n_in,
                              void* d_out, int out_size) {
    const float* mem  = nullptr;
    const float* ctrl = nullptr;
    const float* prev = nullptr;
    for (int i = 0; i < n_in; i++) {
        if (in_sizes[i] == BB * NN * WW)     mem  = (const float*)d_in[i];
        else if (in_sizes[i] == BB * 280)    ctrl = (const float*)d_in[i];
        else if (in_sizes[i] == BB * 4 * NN) prev = (const float*)d_in[i];
    }

    dim3 grid(NCH, BB);
    k_prep  <<<BB,   256>>>(ctrl);
    k_scores<<<grid, 256>>>(mem);
    k_mid   <<<BB,   128>>>();
    k_read  <<<grid, 256>>>(mem, prev);
    k_final <<<BB,   256>>>((float*)d_out);
}

// round 8
// speedup vs baseline: 1.6008x; 1.1010x over previous
#include <cuda_runtime.h>
#include <cstdint>

#define BB 64
#define NN 8192
#define WW 64
#define EPSF 1e-8f
#define NCH 32            // 8192 / 256 rows per block

typedef unsigned long long ull;

// ---------------- scratch (device globals; no allocation allowed) ----------------
__device__ __align__(16) float  g_keys[BB * 256];      // tanh(keys) [b][h][64]
__device__ __align__(16) float  g_nk[BB * 4];          // ||key||
__device__ __align__(16) float  g_beta[BB * 4];
__device__ __align__(16) float4 g_scA[BB * 4];         // {gate, gamma, 0, 0}
__device__ __align__(16) float4 g_scB[BB * 4];         // {sh0, sh1, sh2, 0}
__device__ __align__(16) float g_e[BB * NN * 4];       // [b][n][h]
__device__ float g_parte[BB * 4 * NCH];
__device__ float g_partw[BB * 4 * NCH];
__device__ __align__(16) float g_parto[NCH * BB * 256];// [chunk][b][h*64+w]

__device__ __forceinline__ float softplusf(float x) {
    return (x > 20.f) ? x : log1pf(expf(x));
}
__device__ __forceinline__ ull pk2(float lo, float hi) {
    ull r; asm("mov.b64 %0, {%1, %2};" : "=l"(r) : "f"(lo), "f"(hi)); return r;
}
__device__ __forceinline__ void upk2(ull v, float& lo, float& hi) {
    asm("mov.b64 {%0, %1}, %2;" : "=f"(lo), "=f"(hi) : "l"(v));
}
__device__ __forceinline__ ull ffma2(ull a, ull b, ull c) {
    ull d; asm("fma.rn.f32x2 %0, %1, %2, %3;" : "=l"(d) : "l"(a), "l"(b), "l"(c)); return d;
}

// =====================================================================
// k_prep: tanh(keys), key norms, betas, per-head scalars.  grid 64, block 256.
// =====================================================================
__global__ void __launch_bounds__(256) k_prep(const float* __restrict__ ctrl) {
    __shared__ float sk[256];
    const int b = blockIdx.x, t = threadIdx.x;
    const float* cb = ctrl + b * 280;
    float kv = tanhf(cb[t]);
    sk[t] = kv;
    g_keys[b * 256 + t] = kv;
    __syncthreads();
    if (t < 4) {
        float s = 0.f;
        #pragma unroll
        for (int w = 0; w < 64; w++) { float k = sk[t * 64 + w]; s = fmaf(k, k, s); }
        g_nk[b * 4 + t]   = sqrtf(s);
        g_beta[b * 4 + t] = softplusf(cb[256 + t]);
        float gate  = 1.f / (1.f + expf(-cb[260 + t]));
        float gamma = 1.f + softplusf(cb[276 + t]);
        float a0 = cb[264 + t * 3], a1 = cb[265 + t * 3], a2 = cb[266 + t * 3];
        float mx = fmaxf(a0, fmaxf(a1, a2));
        float e0 = expf(a0 - mx), e1 = expf(a1 - mx), e2 = expf(a2 - mx);
        float inv3 = 1.f / (e0 + e1 + e2);
        g_scA[b * 4 + t] = make_float4(gate, gamma, 0.f, 0.f);
        g_scB[b * 4 + t] = make_float4(e0 * inv3, e1 * inv3, e2 * inv3, 0.f);
    }
}

// =====================================================================
// k_scores: e = exp(beta*(cos-1)) + per-chunk e-sums.
// grid (32, 64), block 256. 256 rows/block. 8 lanes per row (32B chunks):
// perfect per-instruction coalescing AND only 3-level/8-lane butterflies
// shared by 4 rows per warp (3.75 warp-shfl/row).
// =====================================================================
__global__ void __launch_bounds__(256) k_scores(const float* __restrict__ mem) {
    __shared__ float4 s_dot[256];
    __shared__ float  s_nm[256];
    __shared__ float4 s_es[8];

    const int t    = threadIdx.x;
    const int lane = t & 31;
    const int wid  = t >> 5;
    const int c    = lane & 7;       // 16B chunk within my row-half pattern
    const int rq   = lane >> 3;      // row within warp quad
    const int b    = blockIdx.y;
    const int n0   = blockIdx.x * 256;

    // keys for chunks (j*8 + c), j=0,1, all 4 heads -> 16 ull regs
    ull kk[4][2][2];
    #pragma unroll
    for (int h = 0; h < 4; h++)
        #pragma unroll
        for (int j = 0; j < 2; j++) {
            ulonglong2 kv = *(const ulonglong2*)(g_keys + b * 256 + h * 64 + j * 32 + c * 4);
            kk[h][j][0] = kv.x; kk[h][j][1] = kv.y;
        }

    const float4* mem4 = (const float4*)mem + ((size_t)b * NN + n0) * 16;

    #pragma unroll
    for (int it = 0; it < 8; it++) {
        const int rl = it * 32 + wid * 4 + rq;      // local row 0..255
        float4 m0 = mem4[rl * 16 + c];              // instr j=0: 4 rows x 128B contig
        float4 m1 = mem4[rl * 16 + 8 + c];          // instr j=1
        ull p0 = pk2(m0.x, m0.y), p1 = pk2(m0.z, m0.w);
        ull p2 = pk2(m1.x, m1.y), p3 = pk2(m1.z, m1.w);

        ull nm = ffma2(p0, p0, 0ull); nm = ffma2(p1, p1, nm);
        nm = ffma2(p2, p2, nm);       nm = ffma2(p3, p3, nm);
        ull d0 = ffma2(p0, kk[0][0][0], 0ull); d0 = ffma2(p1, kk[0][0][1], d0);
        d0 = ffma2(p2, kk[0][1][0], d0);       d0 = ffma2(p3, kk[0][1][1], d0);
        ull d1 = ffma2(p0, kk[1][0][0], 0ull); d1 = ffma2(p1, kk[1][0][1], d1);
        d1 = ffma2(p2, kk[1][1][0], d1);       d1 = ffma2(p3, kk[1][1][1], d1);
        ull d2 = ffma2(p0, kk[2][0][0], 0ull); d2 = ffma2(p1, kk[2][0][1], d2);
        d2 = ffma2(p2, kk[2][1][0], d2);       d2 = ffma2(p3, kk[2][1][1], d2);
        ull d3 = ffma2(p0, kk[3][0][0], 0ull); d3 = ffma2(p1, kk[3][0][1], d3);
        d3 = ffma2(p2, kk[3][1][0], d3);       d3 = ffma2(p3, kk[3][1][1], d3);

        float lo, hi;
        upk2(nm, lo, hi); float vn = lo + hi;
        upk2(d0, lo, hi); float v0 = lo + hi;
        upk2(d1, lo, hi); float v1 = lo + hi;
        upk2(d2, lo, hi); float v2 = lo + hi;
        upk2(d3, lo, hi); float v3 = lo + hi;
        #pragma unroll
        for (int s = 1; s <= 4; s <<= 1) {          // butterfly within 8-lane group
            vn += __shfl_xor_sync(0xffffffffu, vn, s);
            v0 += __shfl_xor_sync(0xffffffffu, v0, s);
            v1 += __shfl_xor_sync(0xffffffffu, v1, s);
            v2 += __shfl_xor_sync(0xffffffffu, v2, s);
            v3 += __shfl_xor_sync(0xffffffffu, v3, s);
        }
        if (c == 0) {
            s_dot[rl] = make_float4(v0, v1, v2, v3);
            s_nm[rl]  = vn;
        }
    }
    __syncthreads();

    // epilogue: all 256 threads, row t
    {
        float4 d  = s_dot[t];
        float nmr = sqrtf(s_nm[t]);
        float4 nk = *(const float4*)(g_nk + b * 4);
        float4 be = *(const float4*)(g_beta + b * 4);
        float4 e;
        e.x = __expf(be.x * (__fdividef(d.x, nmr * nk.x + EPSF) - 1.f));
        e.y = __expf(be.y * (__fdividef(d.y, nmr * nk.y + EPSF) - 1.f));
        e.z = __expf(be.z * (__fdividef(d.z, nmr * nk.z + EPSF) - 1.f));
        e.w = __expf(be.w * (__fdividef(d.w, nmr * nk.w + EPSF) - 1.f));
        *(float4*)(g_e + ((size_t)b * NN + n0 + t) * 4) = e;

        float4 v = e;
        #pragma unroll
        for (int s = 16; s > 0; s >>= 1) {
            v.x += __shfl_xor_sync(0xffffffffu, v.x, s);
            v.y += __shfl_xor_sync(0xffffffffu, v.y, s);
            v.z += __shfl_xor_sync(0xffffffffu, v.z, s);
            v.w += __shfl_xor_sync(0xffffffffu, v.w, s);
        }
        if (lane == 0) s_es[wid] = v;
    }
    __syncthreads();
    if (t == 0) {
        float4 a = s_es[0];
        #pragma unroll
        for (int i = 1; i < 8; i++) {
            float4 q = s_es[i];
            a.x += q.x; a.y += q.y; a.z += q.z; a.w += q.w;
        }
        float* p = g_parte + b * 4 * NCH + blockIdx.x;
        p[0]       = a.x; p[NCH]     = a.y;
        p[2 * NCH] = a.z; p[3 * NCH] = a.w;
    }
}

// =====================================================================
// k_read: einv + weights prologue + unnormalized partial read.
// grid (32, 64) reversed, block 256, 256 rows/block, 16-iter unrolled mainloop.
// =====================================================================
__global__ void __launch_bounds__(256) k_read(const float* __restrict__ mem,
                                              const float* __restrict__ prev) {
    __shared__ ulonglong2 s_wp[512];      // [r*2 + q]: q=0 heads {0,1}, q=1 heads {2,3}  (8KB)
    __shared__ float      s_einv[4];
    __shared__ float4     s_red[1024];    // [rsub*4+h]*16 + w4   (16KB)
    __shared__ float4     s_pw[8];

    const int t    = threadIdx.x;
    const int lane = t & 31;
    const int wid  = t >> 5;
    const int bx   = (NCH - 1) - blockIdx.x;   // reversed
    const int b    = (BB  - 1) - blockIdx.y;   // reversed
    const int n0   = bx * 256;

    // ---- phase 0: einv[h] = 1 / sum_c parte ----
    if (wid < 4) {
        float v = g_parte[(b * 4 + wid) * NCH + lane];
        #pragma unroll
        for (int s = 16; s > 0; s >>= 1) v += __shfl_xor_sync(0xffffffffu, v, s);
        if (lane == 0) s_einv[wid] = 1.f / v;
    }
    __syncthreads();

    // ---- phase 1: w_sharp for 256 rows x 4 heads (1 row per thread) ----
    {
        const int n   = n0 + t;
        const int nmi = (n - 1) & (NN - 1);
        const int npi = (n + 1) & (NN - 1);
        const float4* eb = (const float4*)g_e + (size_t)b * NN;
        float4 em = eb[nmi], ec = eb[n], ep = eb[npi];
        float emv[4] = {em.x, em.y, em.z, em.w};
        float ecv[4] = {ec.x, ec.y, ec.z, ec.w};
        float epv[4] = {ep.x, ep.y, ep.z, ep.w};

        float ws[4];
        #pragma unroll
        for (int h = 0; h < 4; h++) {
            float4 A  = g_scA[b * 4 + h];
            float4 Bv = g_scB[b * 4 + h];
            float ei  = s_einv[h];
            float gg  = A.x, om = 1.f - gg;
            const float* pb = prev + ((size_t)b * 4 + h) * NN;
            float wim = fmaf(gg, emv[h] * ei, om * pb[nmi]);
            float wic = fmaf(gg, ecv[h] * ei, om * pb[n]);
            float wip = fmaf(gg, epv[h] * ei, om * pb[npi]);
            float wsf = Bv.x * wim + Bv.y * wic + Bv.z * wip;
            ws[h] = __powf(wsf, A.y);     // wsf > 0 always
        }
        ulonglong2 q0; q0.x = pk2(ws[0], ws[0]); q0.y = pk2(ws[1], ws[1]);
        ulonglong2 q1; q1.x = pk2(ws[2], ws[2]); q1.y = pk2(ws[3], ws[3]);
        s_wp[t * 2]     = q0;
        s_wp[t * 2 + 1] = q1;

        float4 v = make_float4(ws[0], ws[1], ws[2], ws[3]);
        #pragma unroll
        for (int s = 16; s > 0; s >>= 1) {
            v.x += __shfl_xor_sync(0xffffffffu, v.x, s);
            v.y += __shfl_xor_sync(0xffffffffu, v.y, s);
            v.z += __shfl_xor_sync(0xffffffffu, v.z, s);
            v.w += __shfl_xor_sync(0xffffffffu, v.w, s);
        }
        if (lane == 0) s_pw[wid] = v;
    }
    __syncthreads();
    if (t == 0) {
        float4 a = s_pw[0];
        #pragma unroll
        for (int i = 1; i < 8; i++) {
            float4 q = s_pw[i];
            a.x += q.x; a.y += q.y; a.z += q.z; a.w += q.w;
        }
        float* p = g_partw + b * 4 * NCH + bx;
        p[0]       = a.x; p[NCH]     = a.y;
        p[2 * NCH] = a.z; p[3 * NCH] = a.w;
    }

    // ---- phase 2: accumulate 256 rows (16 per thread), coalesced LDG ----
    const int rsub = t >> 4;
    const int w4   = t & 15;
    const float4* base = (const float4*)mem + ((size_t)b * NN + n0) * 16 + w4;

    ull a00 = 0, a01 = 0, a10 = 0, a11 = 0, a20 = 0, a21 = 0, a30 = 0, a31 = 0;
    #pragma unroll
    for (int k = 0; k < 16; k++) {
        const int r = k * 16 + rsub;
        float4 m = base[r * 16];
        ulonglong2 wA = s_wp[r * 2];
        ulonglong2 wB = s_wp[r * 2 + 1];
        ull m01 = pk2(m.x, m.y), m23 = pk2(m.z, m.w);
        a00 = ffma2(wA.x, m01, a00); a01 = ffma2(wA.x, m23, a01);
        a10 = ffma2(wA.y, m01, a10); a11 = ffma2(wA.y, m23, a11);
        a20 = ffma2(wB.x, m01, a20); a21 = ffma2(wB.x, m23, a21);
        a30 = ffma2(wB.y, m01, a30); a31 = ffma2(wB.y, m23, a31);
    }

    // ---- phase 3: cross-thread reduction over rsub ----
    {
        ulonglong2 q;
        q.x = a00; q.y = a01; *(ulonglong2*)&s_red[(rsub * 4 + 0) * 16 + w4] = q;
        q.x = a10; q.y = a11; *(ulonglong2*)&s_red[(rsub * 4 + 1) * 16 + w4] = q;
        q.x = a20; q.y = a21; *(ulonglong2*)&s_red[(rsub * 4 + 2) * 16 + w4] = q;
        q.x = a30; q.y = a31; *(ulonglong2*)&s_red[(rsub * 4 + 3) * 16 + w4] = q;
    }
    __syncthreads();
    if (t < 64) {
        const int h = t >> 4, w = t & 15;
        float4 acc = s_red[(0 * 4 + h) * 16 + w];
        #pragma unroll
        for (int k = 1; k < 16; k++) {
            float4 a = s_red[(k * 4 + h) * 16 + w];
            acc.x += a.x; acc.y += a.y; acc.z += a.z; acc.w += a.w;
        }
        // raw partials (normalize in k_final); float4 idx = (bx*64 + b)*64 + t
        *(((float4*)g_parto) + ((size_t)bx * 64 + b) * 64 + t) = acc;
    }
}

// =====================================================================
// k_final: out[b][h][w] = (sum_c parto) / (sum_c partw + EPS). grid 64, block 256.
// =====================================================================
__global__ void __launch_bounds__(256) k_final(float* __restrict__ out) {
    __shared__ float  s_winv[4];
    __shared__ float4 s_acc[4][64];
    const int b = blockIdx.x, t = threadIdx.x;
    const int i4 = t & 63, cg = t >> 6;

    if (t < 128) {
        const int h = t >> 5, lane = t & 31;
        float v = g_partw[(b * 4 + h) * NCH + lane];
        #pragma unroll
        for (int s = 16; s > 0; s >>= 1) v += __shfl_xor_sync(0xffffffffu, v, s);
        if (lane == 0) s_winv[h] = 1.f / (v + EPSF);
    }

    float4 acc = make_float4(0.f, 0.f, 0.f, 0.f);
    const float4* po = (const float4*)g_parto;
    #pragma unroll
    for (int j = 0; j < 8; j++) {
        const int c = cg * 8 + j;
        float4 a = po[((size_t)c * 64 + b) * 64 + i4];
        acc.x += a.x; acc.y += a.y; acc.z += a.z; acc.w += a.w;
    }
    s_acc[cg][i4] = acc;
    __syncthreads();
    if (t < 64) {
        float4 r = s_acc[0][t], c1 = s_acc[1][t], c2 = s_acc[2][t], c3 = s_acc[3][t];
        r.x += c1.x + c2.x + c3.x;
        r.y += c1.y + c2.y + c3.y;
        r.z += c1.z + c2.z + c3.z;
        r.w += c1.w + c2.w + c3.w;
        float inv = s_winv[t >> 4];
        r.x *= inv; r.y *= inv; r.z *= inv; r.w *= inv;
        *(((float4*)out) + b * 64 + t) = r;
    }
}

// =====================================================================
extern "C" void kernel_launch(void* const* d_in, const int* in_sizes, int n_in,
                              void* d_out, int out_size) {
    const float* mem  = nullptr;
    const float* ctrl = nullptr;
    const float* prev = nullptr;
    for (int i = 0; i < n_in; i++) {
        if (in_sizes[i] == BB * NN * WW)     mem  = (const float*)d_in[i];
        else if (in_sizes[i] == BB * 280)    ctrl = (const float*)d_in[i];
        else if (in_sizes[i] == BB * 4 * NN) prev = (const float*)d_in[i];
    }

    dim3 grid(NCH, BB);
    k_prep  <<<BB,   256>>>(ctrl);
    k_scores<<<grid, 256>>>(mem);
    k_read  <<<grid, 256>>>(mem, prev);
    k_final <<<BB,   256>>>((float*)d_out);
}

// round 9
// speedup vs baseline: 1.6182x; 1.0109x over previous
#include <cuda_runtime.h>
#include <cstdint>

#define BB 64
#define NN 8192
#define WW 64
#define EPSF 1e-8f
#define NCH 32            // 8192 / 256 rows per block

typedef unsigned long long ull;

// ---------------- scratch (device globals; no allocation allowed) ----------------
__device__ __align__(16) float g_e[BB * NN * 4];       // [b][n][h]
__device__ float g_parte[BB * 4 * NCH];
__device__ float g_partw[BB * 4 * NCH];
__device__ __align__(16) float g_parto[NCH * BB * 256];// [chunk][b][h*64+w]
__device__ int   g_ctr[BB];                            // per-batch completion counters

__device__ __forceinline__ float softplusf(float x) {
    return (x > 20.f) ? x : log1pf(expf(x));
}
__device__ __forceinline__ ull pk2(float lo, float hi) {
    ull r; asm("mov.b64 %0, {%1, %2};" : "=l"(r) : "f"(lo), "f"(hi)); return r;
}
__device__ __forceinline__ void upk2(ull v, float& lo, float& hi) {
    asm("mov.b64 {%0, %1}, %2;" : "=f"(lo), "=f"(hi) : "l"(v));
}
__device__ __forceinline__ ull ffma2(ull a, ull b, ull c) {
    ull d; asm("fma.rn.f32x2 %0, %1, %2, %3;" : "=l"(d) : "l"(a), "l"(b), "l"(c)); return d;
}

// =====================================================================
// k_scores: e = exp(beta*(cos-1)) + per-chunk e-sums. Keys computed in-block.
// grid (32, 64), block 256. 256 rows/block, 8 lanes per row (16B chunks x2).
// =====================================================================
__global__ void __launch_bounds__(256) k_scores(const float* __restrict__ mem,
                                                const float* __restrict__ ctrl) {
    __shared__ float  s_keys[256];
    __shared__ float  s_nk[4], s_beta[4];
    __shared__ float4 s_dot[256];
    __shared__ float  s_nm[256];
    __shared__ float4 s_es[8];

    const int t    = threadIdx.x;
    const int lane = t & 31;
    const int wid  = t >> 5;
    const int c    = lane & 7;       // 16B chunk id within row half
    const int rq   = lane >> 3;      // row within warp quad
    const int b    = blockIdx.y;
    const int n0   = blockIdx.x * 256;
    const float* cb = ctrl + b * 280;

    s_keys[t] = tanhf(cb[t]);
    if (blockIdx.x == 0 && t == 0) g_ctr[b] = 0;    // reset counter for k_read
    __syncthreads();
    if (t < 4) {
        const float* kk = s_keys + t * 64;
        float s = 0.f;
        #pragma unroll
        for (int w = 0; w < 64; w++) s = fmaf(kk[w], kk[w], s);
        s_nk[t]   = sqrtf(s);
        s_beta[t] = softplusf(cb[256 + t]);
    }
    __syncthreads();

    // keys for chunks (j*8 + c), j=0,1, all 4 heads -> 16 ull regs
    ull kk[4][2][2];
    #pragma unroll
    for (int h = 0; h < 4; h++)
        #pragma unroll
        for (int j = 0; j < 2; j++) {
            float4 kv = *(const float4*)(s_keys + h * 64 + j * 32 + c * 4);
            kk[h][j][0] = pk2(kv.x, kv.y); kk[h][j][1] = pk2(kv.z, kv.w);
        }

    const float4* mem4 = (const float4*)mem + ((size_t)b * NN + n0) * 16;

    #pragma unroll
    for (int it = 0; it < 8; it++) {
        const int rl = it * 32 + wid * 4 + rq;      // local row 0..255
        float4 m0 = mem4[rl * 16 + c];
        float4 m1 = mem4[rl * 16 + 8 + c];
        ull p0 = pk2(m0.x, m0.y), p1 = pk2(m0.z, m0.w);
        ull p2 = pk2(m1.x, m1.y), p3 = pk2(m1.z, m1.w);

        ull nm = ffma2(p0, p0, 0ull); nm = ffma2(p1, p1, nm);
        nm = ffma2(p2, p2, nm);       nm = ffma2(p3, p3, nm);
        ull d0 = ffma2(p0, kk[0][0][0], 0ull); d0 = ffma2(p1, kk[0][0][1], d0);
        d0 = ffma2(p2, kk[0][1][0], d0);       d0 = ffma2(p3, kk[0][1][1], d0);
        ull d1 = ffma2(p0, kk[1][0][0], 0ull); d1 = ffma2(p1, kk[1][0][1], d1);
        d1 = ffma2(p2, kk[1][1][0], d1);       d1 = ffma2(p3, kk[1][1][1], d1);
        ull d2 = ffma2(p0, kk[2][0][0], 0ull); d2 = ffma2(p1, kk[2][0][1], d2);
        d2 = ffma2(p2, kk[2][1][0], d2);       d2 = ffma2(p3, kk[2][1][1], d2);
        ull d3 = ffma2(p0, kk[3][0][0], 0ull); d3 = ffma2(p1, kk[3][0][1], d3);
        d3 = ffma2(p2, kk[3][1][0], d3);       d3 = ffma2(p3, kk[3][1][1], d3);

        float lo, hi;
        upk2(nm, lo, hi); float vn = lo + hi;
        upk2(d0, lo, hi); float v0 = lo + hi;
        upk2(d1, lo, hi); float v1 = lo + hi;
        upk2(d2, lo, hi); float v2 = lo + hi;
        upk2(d3, lo, hi); float v3 = lo + hi;
        #pragma unroll
        for (int s = 1; s <= 4; s <<= 1) {          // 8-lane butterfly
            vn += __shfl_xor_sync(0xffffffffu, vn, s);
            v0 += __shfl_xor_sync(0xffffffffu, v0, s);
            v1 += __shfl_xor_sync(0xffffffffu, v1, s);
            v2 += __shfl_xor_sync(0xffffffffu, v2, s);
            v3 += __shfl_xor_sync(0xffffffffu, v3, s);
        }
        if (c == 0) {
            s_dot[rl] = make_float4(v0, v1, v2, v3);
            s_nm[rl]  = vn;
        }
    }
    __syncthreads();

    // epilogue: all 256 threads, row t
    {
        float4 d  = s_dot[t];
        float nmr = sqrtf(s_nm[t]);
        float4 e;
        e.x = __expf(s_beta[0] * (__fdividef(d.x, nmr * s_nk[0] + EPSF) - 1.f));
        e.y = __expf(s_beta[1] * (__fdividef(d.y, nmr * s_nk[1] + EPSF) - 1.f));
        e.z = __expf(s_beta[2] * (__fdividef(d.z, nmr * s_nk[2] + EPSF) - 1.f));
        e.w = __expf(s_beta[3] * (__fdividef(d.w, nmr * s_nk[3] + EPSF) - 1.f));
        *(float4*)(g_e + ((size_t)b * NN + n0 + t) * 4) = e;

        float4 v = e;
        #pragma unroll
        for (int s = 16; s > 0; s >>= 1) {
            v.x += __shfl_xor_sync(0xffffffffu, v.x, s);
            v.y += __shfl_xor_sync(0xffffffffu, v.y, s);
            v.z += __shfl_xor_sync(0xffffffffu, v.z, s);
            v.w += __shfl_xor_sync(0xffffffffu, v.w, s);
        }
        if (lane == 0) s_es[wid] = v;
    }
    __syncthreads();
    if (t == 0) {
        float4 a = s_es[0];
        #pragma unroll
        for (int i = 1; i < 8; i++) {
            float4 q = s_es[i];
            a.x += q.x; a.y += q.y; a.z += q.z; a.w += q.w;
        }
        float* p = g_parte + b * 4 * NCH + blockIdx.x;
        p[0]       = a.x; p[NCH]     = a.y;
        p[2 * NCH] = a.z; p[3 * NCH] = a.w;
    }
}

// =====================================================================
// k_read: einv + weights prologue + unnormalized partial read; the LAST
// block of each batch (per-b counter) performs that batch's final reduction
// and writes d_out. grid (32, 64) reversed, block 256.
// =====================================================================
__global__ void __launch_bounds__(256) k_read(const float* __restrict__ mem,
                                              const float* __restrict__ prev,
                                              const float* __restrict__ ctrl,
                                              float* __restrict__ out) {
    __shared__ ulonglong2 s_wp[512];      // packed (w,w): [r*2+q], q=0 heads{0,1}, q=1 heads{2,3}
    __shared__ float      s_einv[4], s_winv[4];
    __shared__ float4     s_scA[4], s_scB[4];
    __shared__ float4     s_red[1024];    // 16KB; reused by final reduction
    __shared__ float4     s_pw[8];
    __shared__ int        s_last;

    const int t    = threadIdx.x;
    const int lane = t & 31;
    const int wid  = t >> 5;
    const int bx   = (NCH - 1) - blockIdx.x;   // reversed
    const int b    = (BB  - 1) - blockIdx.y;   // reversed
    const int n0   = bx * 256;

    // ---- phase 0: per-head scalars + einv ----
    if (t < 4) {
        const float* cb = ctrl + b * 280;
        float gate  = 1.f / (1.f + expf(-cb[260 + t]));
        float gamma = 1.f + softplusf(cb[276 + t]);
        float a0 = cb[264 + t * 3], a1 = cb[265 + t * 3], a2 = cb[266 + t * 3];
        float mx = fmaxf(a0, fmaxf(a1, a2));
        float e0 = expf(a0 - mx), e1 = expf(a1 - mx), e2 = expf(a2 - mx);
        float inv3 = 1.f / (e0 + e1 + e2);
        s_scA[t] = make_float4(gate, gamma, 0.f, 0.f);
        s_scB[t] = make_float4(e0 * inv3, e1 * inv3, e2 * inv3, 0.f);
    }
    if (wid < 4) {
        float v = g_parte[(b * 4 + wid) * NCH + lane];
        #pragma unroll
        for (int s = 16; s > 0; s >>= 1) v += __shfl_xor_sync(0xffffffffu, v, s);
        if (lane == 0) s_einv[wid] = 1.f / v;
    }
    __syncthreads();

    // ---- phase 1: w_sharp for 256 rows x 4 heads (1 row per thread) ----
    {
        const int n   = n0 + t;
        const int nmi = (n - 1) & (NN - 1);
        const int npi = (n + 1) & (NN - 1);
        const float4* eb = (const float4*)g_e + (size_t)b * NN;
        float4 em = eb[nmi], ec = eb[n], ep = eb[npi];
        float emv[4] = {em.x, em.y, em.z, em.w};
        float ecv[4] = {ec.x, ec.y, ec.z, ec.w};
        float epv[4] = {ep.x, ep.y, ep.z, ep.w};

        float ws[4];
        #pragma unroll
        for (int h = 0; h < 4; h++) {
            float4 A  = s_scA[h];
            float4 Bv = s_scB[h];
            float ei  = s_einv[h];
            float gg  = A.x, om = 1.f - gg;
            const float* pb = prev + ((size_t)b * 4 + h) * NN;
            float wim = fmaf(gg, emv[h] * ei, om * pb[nmi]);
            float wic = fmaf(gg, ecv[h] * ei, om * pb[n]);
            float wip = fmaf(gg, epv[h] * ei, om * pb[npi]);
            float wsf = Bv.x * wim + Bv.y * wic + Bv.z * wip;
            ws[h] = __powf(wsf, A.y);     // wsf > 0 always
        }
        ulonglong2 q0; q0.x = pk2(ws[0], ws[0]); q0.y = pk2(ws[1], ws[1]);
        ulonglong2 q1; q1.x = pk2(ws[2], ws[2]); q1.y = pk2(ws[3], ws[3]);
        s_wp[t * 2]     = q0;
        s_wp[t * 2 + 1] = q1;

        float4 v = make_float4(ws[0], ws[1], ws[2], ws[3]);
        #pragma unroll
        for (int s = 16; s > 0; s >>= 1) {
            v.x += __shfl_xor_sync(0xffffffffu, v.x, s);
            v.y += __shfl_xor_sync(0xffffffffu, v.y, s);
            v.z += __shfl_xor_sync(0xffffffffu, v.z, s);
            v.w += __shfl_xor_sync(0xffffffffu, v.w, s);
        }
        if (lane == 0) s_pw[wid] = v;
    }
    __syncthreads();
    if (t == 0) {
        float4 a = s_pw[0];
        #pragma unroll
        for (int i = 1; i < 8; i++) {
            float4 q = s_pw[i];
            a.x += q.x; a.y += q.y; a.z += q.z; a.w += q.w;
        }
        float* p = g_partw + b * 4 * NCH + bx;
        p[0]       = a.x; p[NCH]     = a.y;
        p[2 * NCH] = a.z; p[3 * NCH] = a.w;
    }

    // ---- phase 2: accumulate 256 rows (16 per thread), coalesced LDG ----
    const int rsub = t >> 4;
    const int w4   = t & 15;
    const float4* base = (const float4*)mem + ((size_t)b * NN + n0) * 16 + w4;

    ull a00 = 0, a01 = 0, a10 = 0, a11 = 0, a20 = 0, a21 = 0, a30 = 0, a31 = 0;
    #pragma unroll
    for (int k = 0; k < 16; k++) {
        const int r = k * 16 + rsub;
        float4 m = base[r * 16];
        ulonglong2 wA = s_wp[r * 2];
        ulonglong2 wB = s_wp[r * 2 + 1];
        ull m01 = pk2(m.x, m.y), m23 = pk2(m.z, m.w);
        a00 = ffma2(wA.x, m01, a00); a01 = ffma2(wA.x, m23, a01);
        a10 = ffma2(wA.y, m01, a10); a11 = ffma2(wA.y, m23, a11);
        a20 = ffma2(wB.x, m01, a20); a21 = ffma2(wB.x, m23, a21);
        a30 = ffma2(wB.y, m01, a30); a31 = ffma2(wB.y, m23, a31);
    }

    // ---- phase 3: cross-thread reduction over rsub -> g_parto ----
    {
        ulonglong2 q;
        q.x = a00; q.y = a01; *(ulonglong2*)&s_red[(rsub * 4 + 0) * 16 + w4] = q;
        q.x = a10; q.y = a11; *(ulonglong2*)&s_red[(rsub * 4 + 1) * 16 + w4] = q;
        q.x = a20; q.y = a21; *(ulonglong2*)&s_red[(rsub * 4 + 2) * 16 + w4] = q;
        q.x = a30; q.y = a31; *(ulonglong2*)&s_red[(rsub * 4 + 3) * 16 + w4] = q;
    }
    __syncthreads();
    if (t < 64) {
        const int h = t >> 4, w = t & 15;
        float4 acc = s_red[(0 * 4 + h) * 16 + w];
        #pragma unroll
        for (int k = 1; k < 16; k++) {
            float4 a = s_red[(k * 4 + h) * 16 + w];
            acc.x += a.x; acc.y += a.y; acc.z += a.z; acc.w += a.w;
        }
        // raw partials; float4 idx = (bx*64 + b)*64 + t
        *(((float4*)g_parto) + ((size_t)bx * 64 + b) * 64 + t) = acc;
    }

    // ---- phase 4: last block of this batch reduces all chunks -> out ----
    __threadfence();
    __syncthreads();
    if (t == 0) {
        int old = atomicAdd(&g_ctr[b], 1);
        s_last = (old == NCH - 1) ? 1 : 0;
    }
    __syncthreads();
    if (s_last) {
        __threadfence();                  // acquire: see other blocks' stores
        if (t < 128) {
            const int h = t >> 5, ln = t & 31;
            float v = g_partw[(b * 4 + h) * NCH + ln];
            #pragma unroll
            for (int s = 16; s > 0; s >>= 1) v += __shfl_xor_sync(0xffffffffu, v, s);
            if (ln == 0) s_winv[h] = 1.f / (v + EPSF);
        }
        const int cg = t >> 6, i4 = t & 63;
        float4 acc = make_float4(0.f, 0.f, 0.f, 0.f);
        const float4* po = (const float4*)g_parto;
        #pragma unroll
        for (int j = 0; j < 8; j++) {
            const int c = cg * 8 + j;
            float4 a = po[((size_t)c * 64 + b) * 64 + i4];
            acc.x += a.x; acc.y += a.y; acc.z += a.z; acc.w += a.w;
        }
        __syncthreads();                  // s_red free for reuse
        s_red[cg * 64 + i4] = acc;
        __syncthreads();
        if (t < 64) {
            float4 r = s_red[t], c1 = s_red[64 + t], c2 = s_red[128 + t], c3 = s_red[192 + t];
            r.x += c1.x + c2.x + c3.x;
            r.y += c1.y + c2.y + c3.y;
            r.z += c1.z + c2.z + c3.z;
            r.w += c1.w + c2.w + c3.w;
            float inv = s_winv[t >> 4];
            r.x *= inv; r.y *= inv; r.z *= inv; r.w *= inv;
            *(((float4*)out) + b * 64 + t) = r;
        }
    }
}

// =====================================================================
extern "C" void kernel_launch(void* const* d_in, const int* in_sizes, int n_in,
                              void* d_out, int out_size) {
    const float* mem  = nullptr;
    const float* ctrl = nullptr;
    const float* prev = nullptr;
    for (int i = 0; i < n_in; i++) {
        if (in_sizes[i] == BB * NN * WW)     mem  = (const float*)d_in[i];
        else if (in_sizes[i] == BB * 280)    ctrl = (const float*)d_in[i];
        else if (in_sizes[i] == BB * 4 * NN) prev = (const float*)d_in[i];
    }

    dim3 grid(NCH, BB);
    k_scores<<<grid, 256>>>(mem, ctrl);
    k_read  <<<grid, 256>>>(mem, prev, ctrl, (float*)d_out);
}

// round 10
// speedup vs baseline: 1.6951x; 1.0475x over previous
#include <cuda_runtime.h>
#include <cstdint>

#define BB 64
#define NN 8192
#define WW 64
#define EPSF 1e-8f
#define NCB 4             // chunks (blocks) per batch
#define RB 2048           // rows per block

typedef unsigned long long ull;

// ---------------- scratch (device globals; no allocation allowed) ----------------
__device__ __align__(16) float4 g_parte4[BB * NCB];        // per-chunk e sums (per head)
__device__ __align__(16) float4 g_partw4[BB * NCB];        // per-chunk w sums (per head)
__device__ __align__(16) float4 g_parto4[BB * NCB * 64];   // per-chunk output partials
__device__ __align__(16) float4 g_edge[BB][NCB][2];        // boundary e rows [first,last]
__device__ int g_c1[BB];                                   // phase-A arrival counters
__device__ int g_c2[BB];                                   // phase-C arrival counters

__device__ __forceinline__ float softplusf(float x) {
    return (x > 20.f) ? x : log1pf(expf(x));
}
__device__ __forceinline__ ull pk2(float lo, float hi) {
    ull r; asm("mov.b64 %0, {%1, %2};" : "=l"(r) : "f"(lo), "f"(hi)); return r;
}
__device__ __forceinline__ void upk2(ull v, float& lo, float& hi) {
    asm("mov.b64 {%0, %1}, %2;" : "=f"(lo), "=f"(hi) : "l"(v));
}
__device__ __forceinline__ ull ffma2(ull a, ull b, ull c) {
    ull d; asm("fma.rn.f32x2 %0, %1, %2, %3;" : "=l"(d) : "l"(a), "l"(b), "l"(c)); return d;
}

// =====================================================================
// Fused kernel: scores -> (per-batch spin sync) -> weights -> read -> out.
// grid (NCB, BB) = 256 blocks, 256 threads. All blocks co-resident
// (__launch_bounds__(256,2) -> >=296 slots), so per-batch spin is safe.
// =====================================================================
__global__ void __launch_bounds__(256, 2) k_fused(const float* __restrict__ mem,
                                                  const float* __restrict__ ctrl,
                                                  const float* __restrict__ prev,
                                                  float* __restrict__ out) {
    __shared__ float4 s_buf[RB];        // e (phase A/B), then w (phase C), then red  (32KB)
    __shared__ float4 s_dot[256];       // per-slab dots (4KB)
    __shared__ float  s_nm[256];        // per-slab norms (1KB)
    __shared__ float  s_keys[256];
    __shared__ float  s_nk[4], s_beta[4];
    __shared__ float4 s_scA[4], s_scB[4];
    __shared__ float4 s_pw[8];
    __shared__ float4 s_einv, s_winv;
    __shared__ int    s_last;

    const int t    = threadIdx.x;
    const int lane = t & 31;
    const int wid  = t >> 5;
    const int cc   = lane & 7;          // 16B chunk id within row half
    const int rq   = lane >> 3;         // row within warp quad
    const int c    = blockIdx.x;        // chunk 0..3
    const int b    = blockIdx.y;
    const float* cb = ctrl + b * 280;

    // ---- prep: keys + per-head scalars ----
    s_keys[t] = tanhf(cb[t]);
    __syncthreads();
    if (t < 4) {
        const float* kk = s_keys + t * 64;
        float s = 0.f;
        #pragma unroll
        for (int w = 0; w < 64; w++) s = fmaf(kk[w], kk[w], s);
        s_nk[t]   = sqrtf(s);
        s_beta[t] = softplusf(cb[256 + t]);
        float gate  = 1.f / (1.f + expf(-cb[260 + t]));
        float gamma = 1.f + softplusf(cb[276 + t]);
        float a0 = cb[264 + t * 3], a1 = cb[265 + t * 3], a2 = cb[266 + t * 3];
        float mx = fmaxf(a0, fmaxf(a1, a2));
        float e0 = expf(a0 - mx), e1 = expf(a1 - mx), e2 = expf(a2 - mx);
        float inv3 = 1.f / (e0 + e1 + e2);
        s_scA[t] = make_float4(gate, gamma, 0.f, 0.f);
        s_scB[t] = make_float4(e0 * inv3, e1 * inv3, e2 * inv3, 0.f);
    }
    __syncthreads();

    // keys for chunks (j*8 + cc), j=0,1, all 4 heads -> 16 ull regs
    ull kk[4][2][2];
    #pragma unroll
    for (int h = 0; h < 4; h++)
        #pragma unroll
        for (int j = 0; j < 2; j++) {
            float4 kv = *(const float4*)(s_keys + h * 64 + j * 32 + cc * 4);
            kk[h][j][0] = pk2(kv.x, kv.y); kk[h][j][1] = pk2(kv.z, kv.w);
        }

    const float4* mem4 = (const float4*)mem + ((size_t)b * NN + (size_t)c * RB) * 16;

    // ================= Phase A: scores, e -> s_buf =================
    float4 esum = make_float4(0.f, 0.f, 0.f, 0.f);
    for (int slab = 0; slab < 8; slab++) {
        #pragma unroll
        for (int it = 0; it < 8; it++) {
            const int rs = it * 32 + wid * 4 + rq;        // row within slab 0..255
            const int rl = slab * 256 + rs;
            float4 m0 = mem4[rl * 16 + cc];
            float4 m1 = mem4[rl * 16 + 8 + cc];
            ull p0 = pk2(m0.x, m0.y), p1 = pk2(m0.z, m0.w);
            ull p2 = pk2(m1.x, m1.y), p3 = pk2(m1.z, m1.w);

            ull nm = ffma2(p0, p0, 0ull); nm = ffma2(p1, p1, nm);
            nm = ffma2(p2, p2, nm);       nm = ffma2(p3, p3, nm);
            ull d0 = ffma2(p0, kk[0][0][0], 0ull); d0 = ffma2(p1, kk[0][0][1], d0);
            d0 = ffma2(p2, kk[0][1][0], d0);       d0 = ffma2(p3, kk[0][1][1], d0);
            ull d1 = ffma2(p0, kk[1][0][0], 0ull); d1 = ffma2(p1, kk[1][0][1], d1);
            d1 = ffma2(p2, kk[1][1][0], d1);       d1 = ffma2(p3, kk[1][1][1], d1);
            ull d2 = ffma2(p0, kk[2][0][0], 0ull); d2 = ffma2(p1, kk[2][0][1], d2);
            d2 = ffma2(p2, kk[2][1][0], d2);       d2 = ffma2(p3, kk[2][1][1], d2);
            ull d3 = ffma2(p0, kk[3][0][0], 0ull); d3 = ffma2(p1, kk[3][0][1], d3);
            d3 = ffma2(p2, kk[3][1][0], d3);       d3 = ffma2(p3, kk[3][1][1], d3);

            float lo, hi;
            upk2(nm, lo, hi); float vn = lo + hi;
            upk2(d0, lo, hi); float v0 = lo + hi;
            upk2(d1, lo, hi); float v1 = lo + hi;
            upk2(d2, lo, hi); float v2 = lo + hi;
            upk2(d3, lo, hi); float v3 = lo + hi;
            #pragma unroll
            for (int s = 1; s <= 4; s <<= 1) {            // 8-lane butterfly
                vn += __shfl_xor_sync(0xffffffffu, vn, s);
                v0 += __shfl_xor_sync(0xffffffffu, v0, s);
                v1 += __shfl_xor_sync(0xffffffffu, v1, s);
                v2 += __shfl_xor_sync(0xffffffffu, v2, s);
                v3 += __shfl_xor_sync(0xffffffffu, v3, s);
            }
            if (cc == 0) {
                s_dot[rs] = make_float4(v0, v1, v2, v3);
                s_nm[rs]  = vn;
            }
        }
        __syncthreads();
        {   // slab epilogue: all 256 threads, one row each (MUFU spread)
            float4 d  = s_dot[t];
            float nmr = sqrtf(s_nm[t]);
            float4 e;
            e.x = __expf(s_beta[0] * (__fdividef(d.x, nmr * s_nk[0] + EPSF) - 1.f));
            e.y = __expf(s_beta[1] * (__fdividef(d.y, nmr * s_nk[1] + EPSF) - 1.f));
            e.z = __expf(s_beta[2] * (__fdividef(d.z, nmr * s_nk[2] + EPSF) - 1.f));
            e.w = __expf(s_beta[3] * (__fdividef(d.w, nmr * s_nk[3] + EPSF) - 1.f));
            s_buf[slab * 256 + t] = e;
            esum.x += e.x; esum.y += e.y; esum.z += e.z; esum.w += e.w;
        }
        __syncthreads();
    }

    // block e-sum reduction
    #pragma unroll
    for (int s = 16; s > 0; s >>= 1) {
        esum.x += __shfl_xor_sync(0xffffffffu, esum.x, s);
        esum.y += __shfl_xor_sync(0xffffffffu, esum.y, s);
        esum.z += __shfl_xor_sync(0xffffffffu, esum.z, s);
        esum.w += __shfl_xor_sync(0xffffffffu, esum.w, s);
    }
    if (lane == 0) s_pw[wid] = esum;
    __syncthreads();

    // ---- sync 1: publish e-sum + edges, spin until batch complete ----
    if (t == 0) {
        float4 a = s_pw[0];
        #pragma unroll
        for (int i = 1; i < 8; i++) {
            float4 q = s_pw[i];
            a.x += q.x; a.y += q.y; a.z += q.z; a.w += q.w;
        }
        g_parte4[b * NCB + c] = a;
        g_edge[b][c][0] = s_buf[0];
        g_edge[b][c][1] = s_buf[RB - 1];
        __threadfence();                       // release (t0's stores only; t0 stored all)
        atomicAdd(&g_c1[b], 1);
        while (*((volatile int*)&g_c1[b]) < NCB) __nanosleep(32);
        __threadfence();                       // acquire
        float4 p0 = g_parte4[b * NCB + 0], p1 = g_parte4[b * NCB + 1];
        float4 p2 = g_parte4[b * NCB + 2], p3 = g_parte4[b * NCB + 3];
        s_einv.x = 1.f / (p0.x + p1.x + p2.x + p3.x);
        s_einv.y = 1.f / (p0.y + p1.y + p2.y + p3.y);
        s_einv.z = 1.f / (p0.z + p1.z + p2.z + p3.z);
        s_einv.w = 1.f / (p0.w + p1.w + p2.w + p3.w);
    }
    __syncthreads();

    // ================= Phase B: weights (in registers), then overwrite s_buf =================
    float4 wreg[8];
    {
        float4 wacc = make_float4(0.f, 0.f, 0.f, 0.f);
        const float4 edgeL = g_edge[b][(c + NCB - 1) & (NCB - 1)][1];
        const float4 edgeR = g_edge[b][(c + 1) & (NCB - 1)][0];
        const float4 ei4 = s_einv;
        #pragma unroll
        for (int j = 0; j < 8; j++) {
            const int r = j * 256 + t;
            const int n = c * RB + r;
            const int nmi = (n - 1) & (NN - 1);
            const int npi = (n + 1) & (NN - 1);
            float4 ec = s_buf[r];
            float4 em = (r == 0)      ? edgeL : s_buf[r - 1];
            float4 ep = (r == RB - 1) ? edgeR : s_buf[r + 1];
            float emv[4] = {em.x, em.y, em.z, em.w};
            float ecv[4] = {ec.x, ec.y, ec.z, ec.w};
            float epv[4] = {ep.x, ep.y, ep.z, ep.w};
            float eiv[4] = {ei4.x, ei4.y, ei4.z, ei4.w};
            float ws[4];
            #pragma unroll
            for (int h = 0; h < 4; h++) {
                float4 A  = s_scA[h];
                float4 Bv = s_scB[h];
                float gg  = A.x, om = 1.f - gg;
                const float* pb = prev + ((size_t)b * 4 + h) * NN;
                float wim = fmaf(gg, emv[h] * eiv[h], om * pb[nmi]);
                float wic = fmaf(gg, ecv[h] * eiv[h], om * pb[n]);
                float wip = fmaf(gg, epv[h] * eiv[h], om * pb[npi]);
                float wsf = Bv.x * wim + Bv.y * wic + Bv.z * wip;
                ws[h] = __powf(wsf, A.y);       // wsf > 0 always
            }
            wreg[j] = make_float4(ws[0], ws[1], ws[2], ws[3]);
            wacc.x += ws[0]; wacc.y += ws[1]; wacc.z += ws[2]; wacc.w += ws[3];
        }
        __syncthreads();                        // all e reads done
        #pragma unroll
        for (int j = 0; j < 8; j++) s_buf[j * 256 + t] = wreg[j];

        #pragma unroll
        for (int s = 16; s > 0; s >>= 1) {
            wacc.x += __shfl_xor_sync(0xffffffffu, wacc.x, s);
            wacc.y += __shfl_xor_sync(0xffffffffu, wacc.y, s);
            wacc.z += __shfl_xor_sync(0xffffffffu, wacc.z, s);
            wacc.w += __shfl_xor_sync(0xffffffffu, wacc.w, s);
        }
        if (lane == 0) s_pw[wid] = wacc;
    }
    __syncthreads();
    if (t == 0) {
        float4 a = s_pw[0];
        #pragma unroll
        for (int i = 1; i < 8; i++) {
            float4 q = s_pw[i];
            a.x += q.x; a.y += q.y; a.z += q.z; a.w += q.w;
        }
        g_partw4[b * NCB + c] = a;              // fenced later (before c2 add)
    }

    // ================= Phase C: read pass (L2-hot), accumulate =================
    const int rsub = t >> 4;
    const int w4   = t & 15;
    const float4* basec = mem4 + w4;

    ull a00 = 0, a01 = 0, a10 = 0, a11 = 0, a20 = 0, a21 = 0, a30 = 0, a31 = 0;
    #pragma unroll 8
    for (int k = 0; k < 128; k++) {
        const int r = k * 16 + rsub;
        float4 m  = basec[r * 16];
        float4 wv = s_buf[r];                   // broadcast within 16-lane group
        ull w0 = pk2(wv.x, wv.x), w1 = pk2(wv.y, wv.y);
        ull w2 = pk2(wv.z, wv.z), w3 = pk2(wv.w, wv.w);
        ull m01 = pk2(m.x, m.y), m23 = pk2(m.z, m.w);
        a00 = ffma2(w0, m01, a00); a01 = ffma2(w0, m23, a01);
        a10 = ffma2(w1, m01, a10); a11 = ffma2(w1, m23, a11);
        a20 = ffma2(w2, m01, a20); a21 = ffma2(w2, m23, a21);
        a30 = ffma2(w3, m01, a30); a31 = ffma2(w3, m23, a31);
    }

    __syncthreads();                            // w consumed; reuse s_buf as reduction buf
    {
        ulonglong2 q;
        q.x = a00; q.y = a01; *(ulonglong2*)&s_buf[(rsub * 4 + 0) * 16 + w4] = q;
        q.x = a10; q.y = a11; *(ulonglong2*)&s_buf[(rsub * 4 + 1) * 16 + w4] = q;
        q.x = a20; q.y = a21; *(ulonglong2*)&s_buf[(rsub * 4 + 2) * 16 + w4] = q;
        q.x = a30; q.y = a31; *(ulonglong2*)&s_buf[(rsub * 4 + 3) * 16 + w4] = q;
    }
    __syncthreads();
    if (t < 64) {
        const int h = t >> 4, w = t & 15;
        float4 acc = s_buf[(0 * 4 + h) * 16 + w];
        #pragma unroll
        for (int k = 1; k < 16; k++) {
            float4 a = s_buf[(k * 4 + h) * 16 + w];
            acc.x += a.x; acc.y += a.y; acc.z += a.z; acc.w += a.w;
        }
        g_parto4[(b * NCB + c) * 64 + t] = acc;
        __threadfence();                        // release for parto (storing threads only)
    }
    __syncthreads();

    // ---- sync 2: last block of batch reduces + writes out ----
    if (t == 0) {
        __threadfence();                        // release for t0's g_partw store
        int old = atomicAdd(&g_c2[b], 1);
        s_last = (old == NCB - 1) ? 1 : 0;
    }
    __syncthreads();
    if (s_last) {
        if (t == 0) {
            __threadfence();                    // acquire
            float4 q0 = g_partw4[b * NCB + 0], q1 = g_partw4[b * NCB + 1];
            float4 q2 = g_partw4[b * NCB + 2], q3 = g_partw4[b * NCB + 3];
            s_winv.x = 1.f / (q0.x + q1.x + q2.x + q3.x + EPSF);
            s_winv.y = 1.f / (q0.y + q1.y + q2.y + q3.y + EPSF);
            s_winv.z = 1.f / (q0.z + q1.z + q2.z + q3.z + EPSF);
            s_winv.w = 1.f / (q0.w + q1.w + q2.w + q3.w + EPSF);
        }
        __syncthreads();
        if (t < 64) {
            float4 r0 = g_parto4[(b * NCB + 0) * 64 + t];
            float4 r1 = g_parto4[(b * NCB + 1) * 64 + t];
            float4 r2 = g_parto4[(b * NCB + 2) * 64 + t];
            float4 r3 = g_parto4[(b * NCB + 3) * 64 + t];
            float inv = (t < 16) ? s_winv.x : (t < 32) ? s_winv.y
                      : (t < 48) ? s_winv.z : s_winv.w;
            float4 r;
            r.x = (r0.x + r1.x + r2.x + r3.x) * inv;
            r.y = (r0.y + r1.y + r2.y + r3.y) * inv;
            r.z = (r0.z + r1.z + r2.z + r3.z) * inv;
            r.w = (r0.w + r1.w + r2.w + r3.w) * inv;
            *(((float4*)out) + b * 64 + t) = r;
        }
        if (t == 0) {                           // reset counters for next replay
            g_c1[b] = 0;
            g_c2[b] = 0;
        }
    }
}

// =====================================================================
extern "C" void kernel_launch(void* const* d_in, const int* in_sizes, int n_in,
                              void* d_out, int out_size) {
    const float* mem  = nullptr;
    const float* ctrl = nullptr;
    const float* prev = nullptr;
    for (int i = 0; i < n_in; i++) {
        if (in_sizes[i] == BB * NN * WW)     mem  = (const float*)d_in[i];
        else if (in_sizes[i] == BB * 280)    ctrl = (const float*)d_in[i];
        else if (in_sizes[i] == BB * 4 * NN) prev = (const float*)d_in[i];
    }

    dim3 grid(NCB, BB);
    k_fused<<<grid, 256>>>(mem, ctrl, prev, (float*)d_out);
}

// round 12
// speedup vs baseline: 1.7749x; 1.0471x over previous
#include <cuda_runtime.h>
#include <cstdint>

#define BB 64
#define NN 8192
#define WW 64
#define EPSF 1e-8f
#define NCB 8             // chunks (blocks) per batch
#define RB 1024           // rows per block
#define NSLAB (RB / 256)  // 4

typedef unsigned long long ull;

// ---------------- scratch (device globals; no allocation allowed) ----------------
__device__ __align__(16) float4 g_parte4[BB * NCB];        // per-chunk e sums (per head)
__device__ __align__(16) float4 g_partw4[BB * NCB];        // per-chunk w sums (per head)
__device__ __align__(16) float4 g_parto4[BB * NCB * 64];   // per-chunk output partials
__device__ __align__(16) float4 g_edge[BB][NCB][2];        // boundary e rows [first,last]
__device__ int g_c1[BB];                                   // phase-A arrival counters
__device__ int g_c2[BB];                                   // phase-C arrival counters

__device__ __forceinline__ float softplusf(float x) {
    return (x > 20.f) ? x : log1pf(expf(x));
}
__device__ __forceinline__ ull pk2(float lo, float hi) {
    ull r; asm("mov.b64 %0, {%1, %2};" : "=l"(r) : "f"(lo), "f"(hi)); return r;
}
__device__ __forceinline__ void upk2(ull v, float& lo, float& hi) {
    asm("mov.b64 {%0, %1}, %2;" : "=f"(lo), "=f"(hi) : "l"(v));
}
__device__ __forceinline__ ull ffma2(ull a, ull b, ull c) {
    ull d; asm("fma.rn.f32x2 %0, %1, %2, %3;" : "=l"(d) : "l"(a), "l"(b), "l"(c)); return d;
}

// =====================================================================
// Fused kernel: scores -> (per-batch spin sync) -> weights -> read -> out.
// grid (NCB, BB) = 512 blocks, 256 threads, 2 blocks/SM -> 1.73 waves,
// all SMs engaged. Per-batch spin is progress-safe: scheduler issues blocks
// in near-order, so the resident window always contains complete batches.
// =====================================================================
__global__ void __launch_bounds__(256, 2) k_fused(const float* __restrict__ mem,
                                                  const float* __restrict__ ctrl,
                                                  const float* __restrict__ prev,
                                                  float* __restrict__ out) {
    __shared__ float4 s_buf[RB];        // e (A/B), then w (C), then reduction  (16KB)
    __shared__ float4 s_dot[256];       // per-slab dots (4KB)
    __shared__ float  s_nm[256];        // per-slab norms (1KB)
    __shared__ float  s_keys[256];
    __shared__ float  s_nk[4], s_beta[4];
    __shared__ float4 s_scA[4], s_scB[4];
    __shared__ float4 s_pw[8];
    __shared__ float4 s_einv, s_winv;
    __shared__ int    s_last;

    const int t    = threadIdx.x;
    const int lane = t & 31;
    const int wid  = t >> 5;
    const int cc   = lane & 7;          // 16B chunk id within row half
    const int rq   = lane >> 3;         // row within warp quad
    const int c    = blockIdx.x;        // chunk 0..7
    const int b    = blockIdx.y;
    const float* cb = ctrl + b * 280;

    // ---- prep: keys + per-head scalars ----
    s_keys[t] = tanhf(cb[t]);
    __syncthreads();
    if (t < 4) {
        const float* kk = s_keys + t * 64;
        float s = 0.f;
        #pragma unroll
        for (int w = 0; w < 64; w++) s = fmaf(kk[w], kk[w], s);
        s_nk[t]   = sqrtf(s);
        s_beta[t] = softplusf(cb[256 + t]);
        float gate  = 1.f / (1.f + expf(-cb[260 + t]));
        float gamma = 1.f + softplusf(cb[276 + t]);
        float a0 = cb[264 + t * 3], a1 = cb[265 + t * 3], a2 = cb[266 + t * 3];
        float mx = fmaxf(a0, fmaxf(a1, a2));
        float e0 = expf(a0 - mx), e1 = expf(a1 - mx), e2 = expf(a2 - mx);
        float inv3 = 1.f / (e0 + e1 + e2);
        s_scA[t] = make_float4(gate, gamma, 0.f, 0.f);
        s_scB[t] = make_float4(e0 * inv3, e1 * inv3, e2 * inv3, 0.f);
    }
    __syncthreads();

    // keys for chunks (j*8 + cc), j=0,1, all 4 heads -> 16 ull regs
    ull kk[4][2][2];
    #pragma unroll
    for (int h = 0; h < 4; h++)
        #pragma unroll
        for (int j = 0; j < 2; j++) {
            float4 kv = *(const float4*)(s_keys + h * 64 + j * 32 + cc * 4);
            kk[h][j][0] = pk2(kv.x, kv.y); kk[h][j][1] = pk2(kv.z, kv.w);
        }

    const float4* mem4 = (const float4*)mem + ((size_t)b * NN + (size_t)c * RB) * 16;

    // ================= Phase A: scores, e -> s_buf =================
    float4 esum = make_float4(0.f, 0.f, 0.f, 0.f);
    for (int slab = 0; slab < NSLAB; slab++) {
        #pragma unroll
        for (int it = 0; it < 8; it++) {
            const int rs = it * 32 + wid * 4 + rq;        // row within slab 0..255
            const int rl = slab * 256 + rs;
            float4 m0 = mem4[rl * 16 + cc];
            float4 m1 = mem4[rl * 16 + 8 + cc];
            ull p0 = pk2(m0.x, m0.y), p1 = pk2(m0.z, m0.w);
            ull p2 = pk2(m1.x, m1.y), p3 = pk2(m1.z, m1.w);

            ull nm = ffma2(p0, p0, 0ull); nm = ffma2(p1, p1, nm);
            nm = ffma2(p2, p2, nm);       nm = ffma2(p3, p3, nm);
            ull d0 = ffma2(p0, kk[0][0][0], 0ull); d0 = ffma2(p1, kk[0][0][1], d0);
            d0 = ffma2(p2, kk[0][1][0], d0);       d0 = ffma2(p3, kk[0][1][1], d0);
            ull d1 = ffma2(p0, kk[1][0][0], 0ull); d1 = ffma2(p1, kk[1][0][1], d1);
            d1 = ffma2(p2, kk[1][1][0], d1);       d1 = ffma2(p3, kk[1][1][1], d1);
            ull d2 = ffma2(p0, kk[2][0][0], 0ull); d2 = ffma2(p1, kk[2][0][1], d2);
            d2 = ffma2(p2, kk[2][1][0], d2);       d2 = ffma2(p3, kk[2][1][1], d2);
            ull d3 = ffma2(p0, kk[3][0][0], 0ull); d3 = ffma2(p1, kk[3][0][1], d3);
            d3 = ffma2(p2, kk[3][1][0], d3);       d3 = ffma2(p3, kk[3][1][1], d3);

            float lo, hi;
            upk2(nm, lo, hi); float vn = lo + hi;
            upk2(d0, lo, hi); float v0 = lo + hi;
            upk2(d1, lo, hi); float v1 = lo + hi;
            upk2(d2, lo, hi); float v2 = lo + hi;
            upk2(d3, lo, hi); float v3 = lo + hi;
            #pragma unroll
            for (int s = 1; s <= 4; s <<= 1) {            // 8-lane butterfly
                vn += __shfl_xor_sync(0xffffffffu, vn, s);
                v0 += __shfl_xor_sync(0xffffffffu, v0, s);
                v1 += __shfl_xor_sync(0xffffffffu, v1, s);
                v2 += __shfl_xor_sync(0xffffffffu, v2, s);
                v3 += __shfl_xor_sync(0xffffffffu, v3, s);
            }
            if (cc == 0) {
                s_dot[rs] = make_float4(v0, v1, v2, v3);
                s_nm[rs]  = vn;
            }
        }
        __syncthreads();
        {   // slab epilogue: all 256 threads, one row each (MUFU spread)
            float4 d  = s_dot[t];
            float nmr = sqrtf(s_nm[t]);
            float4 e;
            e.x = __expf(s_beta[0] * (__fdividef(d.x, nmr * s_nk[0] + EPSF) - 1.f));
            e.y = __expf(s_beta[1] * (__fdividef(d.y, nmr * s_nk[1] + EPSF) - 1.f));
            e.z = __expf(s_beta[2] * (__fdividef(d.z, nmr * s_nk[2] + EPSF) - 1.f));
            e.w = __expf(s_beta[3] * (__fdividef(d.w, nmr * s_nk[3] + EPSF) - 1.f));
            s_buf[slab * 256 + t] = e;
            esum.x += e.x; esum.y += e.y; esum.z += e.z; esum.w += e.w;
        }
        __syncthreads();
    }

    // block e-sum reduction
    #pragma unroll
    for (int s = 16; s > 0; s >>= 1) {
        esum.x += __shfl_xor_sync(0xffffffffu, esum.x, s);
        esum.y += __shfl_xor_sync(0xffffffffu, esum.y, s);
        esum.z += __shfl_xor_sync(0xffffffffu, esum.z, s);
        esum.w += __shfl_xor_sync(0xffffffffu, esum.w, s);
    }
    if (lane == 0) s_pw[wid] = esum;
    __syncthreads();

    // ---- sync 1: publish e-sum + edges, spin until batch complete ----
    if (t == 0) {
        float4 a = s_pw[0];
        #pragma unroll
        for (int i = 1; i < 8; i++) {
            float4 q = s_pw[i];
            a.x += q.x; a.y += q.y; a.z += q.z; a.w += q.w;
        }
        g_parte4[b * NCB + c] = a;
        g_edge[b][c][0] = s_buf[0];
        g_edge[b][c][1] = s_buf[RB - 1];
        __threadfence();                       // release (t0 performed all these stores)
        atomicAdd(&g_c1[b], 1);
        while (*((volatile int*)&g_c1[b]) < NCB) __nanosleep(32);
        __threadfence();                       // acquire
        float4 a4 = make_float4(0.f, 0.f, 0.f, 0.f);
        #pragma unroll
        for (int i = 0; i < NCB; i++) {
            float4 p = g_parte4[b * NCB + i];
            a4.x += p.x; a4.y += p.y; a4.z += p.z; a4.w += p.w;
        }
        s_einv.x = 1.f / a4.x; s_einv.y = 1.f / a4.y;
        s_einv.z = 1.f / a4.z; s_einv.w = 1.f / a4.w;
    }
    __syncthreads();

    // ================= Phase B: weights (registers), then overwrite s_buf =================
    float4 wreg[NSLAB];
    {
        float4 wacc = make_float4(0.f, 0.f, 0.f, 0.f);
        const float4 edgeL = g_edge[b][(c + NCB - 1) & (NCB - 1)][1];
        const float4 edgeR = g_edge[b][(c + 1) & (NCB - 1)][0];
        const float4 ei4 = s_einv;
        #pragma unroll
        for (int j = 0; j < NSLAB; j++) {
            const int r = j * 256 + t;
            const int n = c * RB + r;
            const int nmi = (n - 1) & (NN - 1);
            const int npi = (n + 1) & (NN - 1);
            float4 ec = s_buf[r];
            float4 em = (r == 0)      ? edgeL : s_buf[r - 1];
            float4 ep = (r == RB - 1) ? edgeR : s_buf[r + 1];
            float emv[4] = {em.x, em.y, em.z, em.w};
            float ecv[4] = {ec.x, ec.y, ec.z, ec.w};
            float epv[4] = {ep.x, ep.y, ep.z, ep.w};
            float eiv[4] = {ei4.x, ei4.y, ei4.z, ei4.w};
            float ws[4];
            #pragma unroll
            for (int h = 0; h < 4; h++) {
                float4 A  = s_scA[h];
                float4 Bv = s_scB[h];
                float gg  = A.x, om = 1.f - gg;
                const float* pb = prev + ((size_t)b * 4 + h) * NN;
                float wim = fmaf(gg, emv[h] * eiv[h], om * pb[nmi]);
                float wic = fmaf(gg, ecv[h] * eiv[h], om * pb[n]);
                float wip = fmaf(gg, epv[h] * eiv[h], om * pb[npi]);
                float wsf = Bv.x * wim + Bv.y * wic + Bv.z * wip;
                ws[h] = __powf(wsf, A.y);       // wsf > 0 always
            }
            wreg[j] = make_float4(ws[0], ws[1], ws[2], ws[3]);
            wacc.x += ws[0]; wacc.y += ws[1]; wacc.z += ws[2]; wacc.w += ws[3];
        }
        __syncthreads();                        // all e reads done
        #pragma unroll
        for (int j = 0; j < NSLAB; j++) s_buf[j * 256 + t] = wreg[j];

        #pragma unroll
        for (int s = 16; s > 0; s >>= 1) {
            wacc.x += __shfl_xor_sync(0xffffffffu, wacc.x, s);
            wacc.y += __shfl_xor_sync(0xffffffffu, wacc.y, s);
            wacc.z += __shfl_xor_sync(0xffffffffu, wacc.z, s);
            wacc.w += __shfl_xor_sync(0xffffffffu, wacc.w, s);
        }
        if (lane == 0) s_pw[wid] = wacc;
    }
    __syncthreads();
    if (t == 0) {
        float4 a = s_pw[0];
        #pragma unroll
        for (int i = 1; i < 8; i++) {
            float4 q = s_pw[i];
            a.x += q.x; a.y += q.y; a.z += q.z; a.w += q.w;
        }
        g_partw4[b * NCB + c] = a;              // fenced before c2 add
    }

    // ================= Phase C: read pass, accumulate =================
    const int rsub = t >> 4;
    const int w4   = t & 15;
    const float4* basec = mem4 + w4;

    ull a00 = 0, a01 = 0, a10 = 0, a11 = 0, a20 = 0, a21 = 0, a30 = 0, a31 = 0;
    #pragma unroll 8
    for (int k = 0; k < RB / 16; k++) {
        const int r = k * 16 + rsub;
        float4 m  = basec[r * 16];
        float4 wv = s_buf[r];                   // 2-address broadcast per warp
        ull w0 = pk2(wv.x, wv.x), w1 = pk2(wv.y, wv.y);
        ull w2 = pk2(wv.z, wv.z), w3 = pk2(wv.w, wv.w);
        ull m01 = pk2(m.x, m.y), m23 = pk2(m.z, m.w);
        a00 = ffma2(w0, m01, a00); a01 = ffma2(w0, m23, a01);
        a10 = ffma2(w1, m01, a10); a11 = ffma2(w1, m23, a11);
        a20 = ffma2(w2, m01, a20); a21 = ffma2(w2, m23, a21);
        a30 = ffma2(w3, m01, a30); a31 = ffma2(w3, m23, a31);
    }

    __syncthreads();                            // w consumed; reuse s_buf as reduction buf
    {
        ulonglong2 q;
        q.x = a00; q.y = a01; *(ulonglong2*)&s_buf[(rsub * 4 + 0) * 16 + w4] = q;
        q.x = a10; q.y = a11; *(ulonglong2*)&s_buf[(rsub * 4 + 1) * 16 + w4] = q;
        q.x = a20; q.y = a21; *(ulonglong2*)&s_buf[(rsub * 4 + 2) * 16 + w4] = q;
        q.x = a30; q.y = a31; *(ulonglong2*)&s_buf[(rsub * 4 + 3) * 16 + w4] = q;
    }
    __syncthreads();
    if (t < 64) {
        const int h = t >> 4, w = t & 15;
        float4 acc = s_buf[(0 * 4 + h) * 16 + w];
        #pragma unroll
        for (int k = 1; k < 16; k++) {
            float4 a = s_buf[(k * 4 + h) * 16 + w];
            acc.x += a.x; acc.y += a.y; acc.z += a.z; acc.w += a.w;
        }
        g_parto4[(b * NCB + c) * 64 + t] = acc;
        __threadfence();                        // release (storing threads only)
    }
    __syncthreads();

    // ---- sync 2: last block of batch reduces + writes out ----
    if (t == 0) {
        __threadfence();                        // release for t0's g_partw store
        int old = atomicAdd(&g_c2[b], 1);
        s_last = (old == NCB - 1) ? 1 : 0;
    }
    __syncthreads();
    if (s_last) {
        if (t == 0) {
            __threadfence();                    // acquire
            float4 a4 = make_float4(EPSF, EPSF, EPSF, EPSF);
            #pragma unroll
            for (int i = 0; i < NCB; i++) {
                float4 q = g_partw4[b * NCB + i];
                a4.x += q.x; a4.y += q.y; a4.z += q.z; a4.w += q.w;
            }
            s_winv.x = 1.f / a4.x; s_winv.y = 1.f / a4.y;
            s_winv.z = 1.f / a4.z; s_winv.w = 1.f / a4.w;
        }
        __syncthreads();
        if (t < 64) {
            float4 r = make_float4(0.f, 0.f, 0.f, 0.f);
            #pragma unroll
            for (int i = 0; i < NCB; i++) {
                float4 a = g_parto4[(b * NCB + i) * 64 + t];
                r.x += a.x; r.y += a.y; r.z += a.z; r.w += a.w;
            }
            float inv = (t < 16) ? s_winv.x : (t < 32) ? s_winv.y
                      : (t < 48) ? s_winv.z : s_winv.w;
            r.x *= inv; r.y *= inv; r.z *= inv; r.w *= inv;
            *(((float4*)out) + b * 64 + t) = r;
        }
        if (t == 0) {                           // reset counters for next replay
            g_c1[b] = 0;
            g_c2[b] = 0;
        }
    }
}

// =====================================================================
extern "C" void kernel_launch(void* const* d_in, const int* in_sizes, int n_in,
                              void* d_out, int out_size) {
    const float* mem  = nullptr;
    const float* ctrl = nullptr;
    const float* prev = nullptr;
    for (int i = 0; i < n_in; i++) {
        if (in_sizes[i] == BB * NN * WW)     mem  = (const float*)d_in[i];
        else if (in_sizes[i] == BB * 280)    ctrl = (const float*)d_in[i];
        else if (in_sizes[i] == BB * 4 * NN) prev = (const float*)d_in[i];
    }

    dim3 grid(NCB, BB);
    k_fused<<<grid, 256>>>(mem, ctrl, prev, (float*)d_out);
}